// round 12
// baseline (speedup 1.0000x reference)
#include <cuda_runtime.h>
#include <cuda_fp16.h>
#include <cstdint>
#include <cstddef>

// Problem constants
#define BB   16
#define CC   512
#define NN   4096
#define NH   8
#define HD   64
#define EPS  1e-6f
#define NGRP 4
#define GB   (BB / NGRP)   // batches per group = 4

// ---------------------------------------------------------------------------
// Scratch (device globals: allocation-free rule)
// ---------------------------------------------------------------------------
__device__ __half g_qkh[(size_t)BB * 2 * CC * NN]; // [B][1024][4096] relu(qk) fp16
__device__ float g_kvp[(size_t)32 * 128 * 65 * 64];// split-K partials (32 chunks)
__device__ float g_kv [(size_t)128 * 65 * 64];     // [B*nh][65][64] fp32

// fp16 activations, [B][N][C] K-major
__device__ __half g_xq[(size_t)BB * NN * CC];      // x + pos
__device__ __half g_xv[(size_t)BB * NN * CC];      // x
__device__ __half g_ao[(size_t)BB * NN * CC];      // attn output (transposed)
// weights fp16, [O][C] K-major
__device__ __half g_wqk[1024 * 512];
__device__ __half g_wv [512 * 512];
__device__ __half g_wo [512 * 512];

// ---------------------------------------------------------------------------
// Helpers
// ---------------------------------------------------------------------------
__device__ __forceinline__ uint32_t smem_u32(const void* p) {
    uint32_t a;
    asm("{ .reg .u64 t; cvta.to.shared.u64 t, %1; cvt.u32.u64 %0, t; }" : "=r"(a) : "l"(p));
    return a;
}
#define SWZ128(off) ((off) ^ (((off) >> 3) & 0x70))
#define ONES2 0x3C003C00u

__device__ __forceinline__ void cp_async16(uint32_t s, const void* g) {
    asm volatile("cp.async.cg.shared.global [%0], [%1], 16;" :: "r"(s), "l"(g));
}
#define CP_COMMIT() asm volatile("cp.async.commit_group;" ::: "memory")
#define CP_WAIT(n)  asm volatile("cp.async.wait_group %0;" :: "n"(n) : "memory")

__device__ __forceinline__ void ldmatrix_x4(uint32_t* r, uint32_t addr) {
    asm volatile("ldmatrix.sync.aligned.m8n8.x4.shared.b16 {%0,%1,%2,%3}, [%4];"
                 : "=r"(r[0]), "=r"(r[1]), "=r"(r[2]), "=r"(r[3]) : "r"(addr));
}
__device__ __forceinline__ void mma_f16(float* d, const uint32_t* a, const uint32_t* b) {
    asm volatile(
        "mma.sync.aligned.m16n8k16.row.col.f32.f16.f16.f32 "
        "{%0,%1,%2,%3}, {%4,%5,%6,%7}, {%8,%9}, {%0,%1,%2,%3};"
        : "+f"(d[0]), "+f"(d[1]), "+f"(d[2]), "+f"(d[3])
        : "r"(a[0]), "r"(a[1]), "r"(a[2]), "r"(a[3]), "r"(b[0]), "r"(b[1]));
}

// 128-thread GEMM config: BM=128, BN=128, BK=64, warp tile 64x64, 3 stages.
#define BKB 128
#define B_OFF  16384
#define STG    32768
#define GEMM_SMEM (3 * STG)

// ---------------------------------------------------------------------------
// qk / o projection GEMM:  Y[O,N] = W[O,C] @ X[C,N]  (batches bz0 + blockIdx.z)
// ---------------------------------------------------------------------------
template<bool RELU, bool HOUT>
__global__ __launch_bounds__(128, 2) void gemm_tc(
    const __half* __restrict__ A, const __half* __restrict__ Bx,
    void* __restrict__ Yv, int O, int bz0)
{
    extern __shared__ __align__(1024) char smem[];
    const uint32_t sbase = smem_u32(smem);
    const int tid  = threadIdx.x;
    const int wid  = tid >> 5;
    const int lane = tid & 31;
    const int wm   = wid & 1;
    const int wn   = wid >> 1;

    const int n0 = blockIdx.x * 128;
    const int o0 = blockIdx.y * 128;
    const int bz = bz0 + blockIdx.z;

    const __half* Bb = Bx + (size_t)bz * NN * CC;

    auto load_stage = [&](int ck, int st) {
        const int k0 = ck * 64;
        const uint32_t sb = sbase + st * STG;
        #pragma unroll
        for (int i = 0; i < 8; i++) {
            int c = tid + i * 128;
            int row = c >> 3, cc = c & 7;
            cp_async16(sb + SWZ128((uint32_t)(row * BKB + cc * 16)),
                       A + (size_t)(o0 + row) * CC + k0 + cc * 8);
        }
        #pragma unroll
        for (int i = 0; i < 8; i++) {
            int c = tid + i * 128;
            int row = c >> 3, cc = c & 7;
            cp_async16(sb + B_OFF + SWZ128((uint32_t)(row * BKB + cc * 16)),
                       Bb + (size_t)(n0 + row) * CC + k0 + cc * 8);
        }
        CP_COMMIT();
    };

    float acc[4][8][4];
    #pragma unroll
    for (int mf = 0; mf < 4; mf++)
        #pragma unroll
        for (int nf = 0; nf < 8; nf++)
            #pragma unroll
            for (int e = 0; e < 4; e++) acc[mf][nf][e] = 0.f;

    load_stage(0, 0);
    load_stage(1, 1);
    CP_WAIT(1);
    __syncthreads();

    const int a_row  = wm * 64 + (lane & 15);
    const int a_coff = (lane >> 4) * 16;
    const int b_row  = wn * 64 + ((lane >> 4) << 3) + (lane & 7);
    const int b_coff = ((lane >> 3) & 1) * 16;

    for (int it = 0; it < 8; it++) {
        const uint32_t sb = sbase + (it % 3) * STG;
        #pragma unroll
        for (int kk = 0; kk < 4; kk++) {
            uint32_t a[4][4], b[8][2];
            #pragma unroll
            for (int mf = 0; mf < 4; mf++)
                ldmatrix_x4(a[mf], sb +
                            SWZ128((uint32_t)((a_row + mf * 16) * BKB + kk * 32 + a_coff)));
            #pragma unroll
            for (int ng = 0; ng < 4; ng++) {
                uint32_t r[4];
                ldmatrix_x4(r, sb + B_OFF +
                            SWZ128((uint32_t)((b_row + ng * 16) * BKB + kk * 32 + b_coff)));
                b[ng * 2][0] = r[0];  b[ng * 2][1] = r[1];
                b[ng * 2 + 1][0] = r[2];  b[ng * 2 + 1][1] = r[3];
            }
            #pragma unroll
            for (int mf = 0; mf < 4; mf++)
                #pragma unroll
                for (int nf = 0; nf < 8; nf++)
                    mma_f16(acc[mf][nf], a[mf], b[nf]);
        }
        if (it + 2 < 8) {
            load_stage(it + 2, (it + 2) % 3);
            CP_WAIT(1);
        } else {
            CP_WAIT(0);
        }
        __syncthreads();
    }

    const int er = lane >> 2;
    const int ec = (lane & 3) * 2;
    #pragma unroll
    for (int mf = 0; mf < 4; mf++) {
        #pragma unroll
        for (int nf = 0; nf < 8; nf++) {
            const int orow = o0 + wm * 64 + mf * 16 + er;
            const int ocol = n0 + wn * 64 + nf * 8 + ec;
            float v0x = acc[mf][nf][0], v0y = acc[mf][nf][1];
            float v1x = acc[mf][nf][2], v1y = acc[mf][nf][3];
            if (RELU) {
                v0x = fmaxf(v0x, 0.f); v0y = fmaxf(v0y, 0.f);
                v1x = fmaxf(v1x, 0.f); v1y = fmaxf(v1y, 0.f);
            }
            if (HOUT) {
                __half* Yb = (__half*)Yv + (size_t)bz * O * NN;
                *(__half2*)&Yb[(size_t)orow * NN + ocol] = __floats2half2_rn(v0x, v0y);
                *(__half2*)&Yb[(size_t)(orow + 8) * NN + ocol] = __floats2half2_rn(v1x, v1y);
            } else {
                float* Yb = (float*)Yv + (size_t)bz * O * NN;
                *(float2*)&Yb[(size_t)orow * NN + ocol]       = make_float2(v0x, v0y);
                *(float2*)&Yb[(size_t)(orow + 8) * NN + ocol] = make_float2(v1x, v1y);
            }
        }
    }
}

// ---------------------------------------------------------------------------
// Fused v-GEMM + kv (batches bz0 + blockIdx.z)
// ---------------------------------------------------------------------------
#define VP 136
#define KV_KOFF 34816

__global__ __launch_bounds__(128, 2) void gemm_v_kv(
    const __half* __restrict__ A, const __half* __restrict__ Bx,
    const __half* __restrict__ qk, float* __restrict__ kvp, int bz0)
{
    extern __shared__ __align__(1024) char smem[];
    const uint32_t sbase = smem_u32(smem);
    const int tid  = threadIdx.x;
    const int wid  = tid >> 5;
    const int lane = tid & 31;
    const int wm   = wid & 1;
    const int wn   = wid >> 1;

    const int n0 = blockIdx.x * 128;
    const int o0 = blockIdx.y * 128;
    const int bz = bz0 + blockIdx.z;

    const __half* Bb = Bx + (size_t)bz * NN * CC;

    auto load_stage = [&](int ck, int st) {
        const int k0 = ck * 64;
        const uint32_t sb = sbase + st * STG;
        #pragma unroll
        for (int i = 0; i < 8; i++) {
            int c = tid + i * 128;
            int row = c >> 3, cc = c & 7;
            cp_async16(sb + SWZ128((uint32_t)(row * BKB + cc * 16)),
                       A + (size_t)(o0 + row) * CC + k0 + cc * 8);
        }
        #pragma unroll
        for (int i = 0; i < 8; i++) {
            int c = tid + i * 128;
            int row = c >> 3, cc = c & 7;
            cp_async16(sb + B_OFF + SWZ128((uint32_t)(row * BKB + cc * 16)),
                       Bb + (size_t)(n0 + row) * CC + k0 + cc * 8);
        }
        CP_COMMIT();
    };

    float acc[4][8][4];
    #pragma unroll
    for (int mf = 0; mf < 4; mf++)
        #pragma unroll
        for (int nf = 0; nf < 8; nf++)
            #pragma unroll
            for (int e = 0; e < 4; e++) acc[mf][nf][e] = 0.f;

    load_stage(0, 0);
    load_stage(1, 1);
    CP_WAIT(1);
    __syncthreads();

    const int a_row  = wm * 64 + (lane & 15);
    const int a_coff = (lane >> 4) * 16;
    const int b_row  = wn * 64 + ((lane >> 4) << 3) + (lane & 7);
    const int b_coff = ((lane >> 3) & 1) * 16;

    for (int it = 0; it < 8; it++) {
        const uint32_t sb = sbase + (it % 3) * STG;
        #pragma unroll
        for (int kk = 0; kk < 4; kk++) {
            uint32_t a[4][4], b[8][2];
            #pragma unroll
            for (int mf = 0; mf < 4; mf++)
                ldmatrix_x4(a[mf], sb +
                            SWZ128((uint32_t)((a_row + mf * 16) * BKB + kk * 32 + a_coff)));
            #pragma unroll
            for (int ng = 0; ng < 4; ng++) {
                uint32_t r[4];
                ldmatrix_x4(r, sb + B_OFF +
                            SWZ128((uint32_t)((b_row + ng * 16) * BKB + kk * 32 + b_coff)));
                b[ng * 2][0] = r[0];  b[ng * 2][1] = r[1];
                b[ng * 2 + 1][0] = r[2];  b[ng * 2 + 1][1] = r[3];
            }
            #pragma unroll
            for (int mf = 0; mf < 4; mf++)
                #pragma unroll
                for (int nf = 0; nf < 8; nf++)
                    mma_f16(acc[mf][nf], a[mf], b[nf]);
        }
        if (it + 2 < 8) {
            load_stage(it + 2, (it + 2) % 3);
            CP_WAIT(1);
        } else {
            CP_WAIT(0);
        }
        __syncthreads();
    }

    // ---- epilogue: v tile (fp16) -> smem [128][VP]; k tile -> smem ----
    __half* sv = (__half*)smem;
    const int er = lane >> 2;
    const int ec = (lane & 3) * 2;
    #pragma unroll
    for (int mf = 0; mf < 4; mf++) {
        #pragma unroll
        for (int nf = 0; nf < 8; nf++) {
            const int lr = wm * 64 + mf * 16 + er;
            const int lc = wn * 64 + nf * 8 + ec;
            *(__half2*)&sv[lr * VP + lc] =
                __floats2half2_rn(acc[mf][nf][0], acc[mf][nf][1]);
            *(__half2*)&sv[(lr + 8) * VP + lc] =
                __floats2half2_rn(acc[mf][nf][2], acc[mf][nf][3]);
        }
    }
    const __half* kb = qk + ((size_t)bz * 2 * CC + CC + o0) * NN + n0;
    #pragma unroll
    for (int i = 0; i < 16; i++) {
        int idx = tid + i * 128;
        int r = idx >> 4, c = idx & 15;
        cp_async16(sbase + KV_KOFF + (uint32_t)(r * 272 + c * 16),
                   kb + (size_t)r * NN + c * 8);
    }
    CP_COMMIT();
    CP_WAIT(0);
    __syncthreads();

    const int dgrp = wid;
    const int arow2 = lane & 15;
    const int acoff2 = (lane >> 4) * 16;
    const int bcoff2 = ((lane >> 3) & 1) * 16;
    const uint32_t ones[4] = {ONES2, ONES2, ONES2, ONES2};

    for (int head = 0; head < 2; head++) {
        float kacc[5][2][4];
        #pragma unroll
        for (int m = 0; m < 5; m++)
            #pragma unroll
            for (int nt = 0; nt < 2; nt++)
                #pragma unroll
                for (int e = 0; e < 4; e++) kacc[m][nt][e] = 0.f;

        const int brow2 = head * 64 + dgrp * 16 + ((lane >> 4) << 3) + (lane & 7);
        #pragma unroll
        for (int ks = 0; ks < 8; ks++) {
            uint32_t bf[4];
            ldmatrix_x4(bf, sbase + KV_KOFF + (uint32_t)(brow2 * 272 + ks * 32 + bcoff2));
            uint32_t b0[2] = {bf[0], bf[1]}, b1[2] = {bf[2], bf[3]};
            #pragma unroll
            for (int m = 0; m < 4; m++) {
                uint32_t a[4];
                ldmatrix_x4(a, sbase +
                            (uint32_t)((head * 64 + m * 16 + arow2) * 272 + ks * 32 + acoff2));
                mma_f16(kacc[m][0], a, b0);
                mma_f16(kacc[m][1], a, b1);
            }
            mma_f16(kacc[4][0], ones, b0);
            mma_f16(kacc[4][1], ones, b1);
        }

        const int bh = bz * 8 + blockIdx.y * 2 + head;
        float* outb = kvp + (size_t)blockIdx.x * (128 * 4160) + (size_t)bh * 4160;
        #pragma unroll
        for (int m = 0; m < 4; m++)
            #pragma unroll
            for (int nt = 0; nt < 2; nt++) {
                const int e = m * 16 + (lane >> 2);
                const int d = dgrp * 16 + nt * 8 + 2 * (lane & 3);
                *(float2*)&outb[e * 64 + d]       = make_float2(kacc[m][nt][0], kacc[m][nt][1]);
                *(float2*)&outb[(e + 8) * 64 + d] = make_float2(kacc[m][nt][2], kacc[m][nt][3]);
            }
        if (lane < 4) {
            #pragma unroll
            for (int nt = 0; nt < 2; nt++) {
                const int d = dgrp * 16 + nt * 8 + 2 * lane;
                *(float2*)&outb[4096 + d] = make_float2(kacc[4][nt][0], kacc[4][nt][1]);
            }
        }
    }
}

// ---------------------------------------------------------------------------
// Weight convert (all three in one launch)
// ---------------------------------------------------------------------------
__global__ void conv_w_all(const float* __restrict__ wqk, const float* __restrict__ wv,
                           const float* __restrict__ wo,
                           __half* __restrict__ oq, __half* __restrict__ ov,
                           __half* __restrict__ oo)
{
    int i = blockIdx.x * 256 + threadIdx.x;
    if (i < 524288) {
        oq[i] = __float2half_rn(wqk[i]);
    } else if (i < 786432) {
        int j = i - 524288; ov[j] = __float2half_rn(wv[j]);
    } else if (i < 1048576) {
        int j = i - 786432; oo[j] = __float2half_rn(wo[j]);
    }
}

// ---------------------------------------------------------------------------
// Transpose + fp16 convert (batches bz0 + blockIdx.z)
// ---------------------------------------------------------------------------
__global__ __launch_bounds__(256) void conv_xt_kernel(
    const float* __restrict__ x, const float* __restrict__ pos,
    __half* __restrict__ xq, __half* __restrict__ xv, int bz0)
{
    __shared__ float sA[64][65];
    __shared__ float sB[64][65];

    const int tid = threadIdx.x;
    const int n0 = blockIdx.x * 64;
    const int c0 = blockIdx.y * 64;
    const int bz = bz0 + blockIdx.z;

    const float* i0 = x   + (size_t)bz * CC * NN;
    const float* i1 = pos + (size_t)bz * CC * NN;

    #pragma unroll
    for (int i = 0; i < 4; i++) {
        int idx = i * 256 + tid;
        int rc = idx >> 4, cn = (idx & 15) * 4;
        float4 xv4 = *(const float4*)&i0[(size_t)(c0 + rc) * NN + n0 + cn];
        float4 pv4 = *(const float4*)&i1[(size_t)(c0 + rc) * NN + n0 + cn];
        sA[rc][cn]     = xv4.x + pv4.x;
        sA[rc][cn + 1] = xv4.y + pv4.y;
        sA[rc][cn + 2] = xv4.z + pv4.z;
        sA[rc][cn + 3] = xv4.w + pv4.w;
        sB[rc][cn]     = xv4.x;
        sB[rc][cn + 1] = xv4.y;
        sB[rc][cn + 2] = xv4.z;
        sB[rc][cn + 3] = xv4.w;
    }
    __syncthreads();

    const size_t obase = ((size_t)bz * NN + n0) * CC + c0;
    #pragma unroll
    for (int i = 0; i < 8; i++) {
        int idx = i * 256 + tid;
        int nr = idx >> 5, cp = idx & 31;
        size_t oa = obase + (size_t)nr * CC + cp * 2;
        __half2 hq, hv;
        hq.x = __float2half_rn(sA[cp * 2][nr]);
        hq.y = __float2half_rn(sA[cp * 2 + 1][nr]);
        hv.x = __float2half_rn(sB[cp * 2][nr]);
        hv.y = __float2half_rn(sB[cp * 2 + 1][nr]);
        *(__half2*)(xq + oa) = hq;
        *(__half2*)(xv + oa) = hv;
    }
}

// ---------------------------------------------------------------------------
// kv reduce for one group of bh (32 bh per group)
// ---------------------------------------------------------------------------
__global__ void kv_reduce(const float* __restrict__ kvp, float* __restrict__ kvout,
                          int bh0)
{
    int i = blockIdx.x * 256 + threadIdx.x;
    if (i < GB * 8 * 4160) {
        size_t j = (size_t)bh0 * 4160 + i;
        float s = 0.f;
        #pragma unroll
        for (int c = 0; c < 32; c++) s += kvp[(size_t)c * (128 * 4160) + j];
        kvout[j] = s;
    }
}

// ---------------------------------------------------------------------------
// attn (tensor cores): out[e,n] = (kv @ q)[e,n] / (ksum@q[n] + EPS)
// ---------------------------------------------------------------------------
#define AT_AH 0
#define AT_AL 10240
#define AT_B  20480
#define AT_SCR 36864
#define ATTN_SMEM 55296

__global__ __launch_bounds__(128) void attn_tc_kernel(
    const __half* __restrict__ qk, const float* __restrict__ kv,
    __half* __restrict__ ao, int bh0)
{
    extern __shared__ __align__(1024) char smem[];
    const uint32_t sbase = smem_u32(smem);
    __half* S1   = (__half*)(smem + AT_SCR);
    __half* sOut = (__half*)(smem + AT_SCR);

    const int tid  = threadIdx.x;
    const int wid  = tid >> 5;
    const int lane = tid & 31;
    const int bh   = bh0 + blockIdx.y;
    const int b = bh >> 3, h = bh & 7;
    const int n0 = blockIdx.x * 128;

    const __half* qbase = qk + ((size_t)b * 2 * CC + h * HD) * NN + n0;
    #pragma unroll
    for (int i = 0; i < 8; i++) {
        int idx = tid + i * 128;
        int d = idx >> 4, j = idx & 15;
        cp_async16(sbase + AT_SCR + (uint32_t)(d * 288 + j * 16),
                   qbase + (size_t)d * NN + j * 8);
    }
    CP_COMMIT();

    {
        uint4 z = {0, 0, 0, 0};
        for (int i = tid; i < 1280; i += 128)
            *(uint4*)(smem + AT_AH + i * 16) = z;
    }
    __syncthreads();
    const float* kvb = kv + (size_t)bh * 4160;
    for (int i = tid; i < 4160; i += 128) {
        int e = i >> 6, d = i & 63;
        float f = kvb[i];
        __half hi = __float2half_rn(f);
        __half lo = __float2half_rn(f - __half2float(hi));
        uint32_t off = SWZ128((uint32_t)(e * 128 + d * 2));
        *(__half*)(smem + AT_AH + off) = hi;
        *(__half*)(smem + AT_AL + off) = lo;
    }
    CP_WAIT(0);
    __syncthreads();

    {
        union { __half hh[8]; uint4 u; } pk;
        const int n = tid;
        #pragma unroll
        for (int j = 0; j < 8; j++) {
            #pragma unroll
            for (int d2 = 0; d2 < 8; d2++)
                pk.hh[d2] = S1[(j * 8 + d2) * 144 + n];
            *(uint4*)(smem + AT_B + SWZ128((uint32_t)(n * 128 + j * 16))) = pk.u;
        }
    }
    __syncthreads();

    float acc[5][4][4];
    #pragma unroll
    for (int m = 0; m < 5; m++)
        #pragma unroll
        for (int nt = 0; nt < 4; nt++)
            #pragma unroll
            for (int e = 0; e < 4; e++) acc[m][nt][e] = 0.f;

    const int a_row  = lane & 15;
    const int a_coff = (lane >> 4) * 16;
    const int b_coff = ((lane >> 3) & 1) * 16;

    #pragma unroll
    for (int ks = 0; ks < 4; ks++) {
        uint32_t ah[5][4], al[5][4], bfr[4][2];
        #pragma unroll
        for (int m = 0; m < 5; m++) {
            const uint32_t so = SWZ128((uint32_t)((m * 16 + a_row) * 128 + ks * 32 + a_coff));
            ldmatrix_x4(ah[m], sbase + AT_AH + so);
            ldmatrix_x4(al[m], sbase + AT_AL + so);
        }
        #pragma unroll
        for (int g = 0; g < 2; g++) {
            const int brow = wid * 32 + g * 16 + ((lane >> 4) << 3) + (lane & 7);
            uint32_t r[4];
            ldmatrix_x4(r, sbase + AT_B + SWZ128((uint32_t)(brow * 128 + ks * 32 + b_coff)));
            bfr[g * 2][0] = r[0];  bfr[g * 2][1] = r[1];
            bfr[g * 2 + 1][0] = r[2];  bfr[g * 2 + 1][1] = r[3];
        }
        #pragma unroll
        for (int m = 0; m < 5; m++)
            #pragma unroll
            for (int nt = 0; nt < 4; nt++) {
                mma_f16(acc[m][nt], ah[m], bfr[nt]);
                mma_f16(acc[m][nt], al[m], bfr[nt]);
            }
    }

    #pragma unroll
    for (int nt = 0; nt < 4; nt++) {
        float den0 = __shfl_sync(0xffffffffu, acc[4][nt][0], lane & 3);
        float den1 = __shfl_sync(0xffffffffu, acc[4][nt][1], lane & 3);
        float inv0 = 1.f / (den0 + EPS);
        float inv1 = 1.f / (den1 + EPS);
        const int n = wid * 32 + nt * 8 + 2 * (lane & 3);
        #pragma unroll
        for (int m = 0; m < 4; m++) {
            const int e = m * 16 + (lane >> 2);
            sOut[n * 72 + e]           = __float2half_rn(acc[m][nt][0] * inv0);
            sOut[(n + 1) * 72 + e]     = __float2half_rn(acc[m][nt][1] * inv1);
            sOut[n * 72 + e + 8]       = __float2half_rn(acc[m][nt][2] * inv0);
            sOut[(n + 1) * 72 + e + 8] = __float2half_rn(acc[m][nt][3] * inv1);
        }
    }
    __syncthreads();

    {
        const int n = tid;
        __half* dst = ao + ((size_t)b * NN + n0 + n) * CC + h * HD;
        #pragma unroll
        for (int j = 0; j < 8; j++)
            *(uint4*)(dst + j * 8) = *(uint4*)(sOut + n * 72 + j * 8);
    }
}

// ---------------------------------------------------------------------------
extern "C" void kernel_launch(void* const* d_in, const int* in_sizes, int n_in,
                              void* d_out, int out_size)
{
    const float* x    = (const float*)d_in[0];
    const float* pos  = (const float*)d_in[1];
    const float* w_qk = (const float*)d_in[2];
    const float* w_v  = (const float*)d_in[3];
    const float* w_o  = (const float*)d_in[4];
    float* out = (float*)d_out;

    __half *qk;
    float *kvp, *kvr;
    cudaGetSymbolAddress((void**)&qk,  g_qkh);
    cudaGetSymbolAddress((void**)&kvp, g_kvp);
    cudaGetSymbolAddress((void**)&kvr, g_kv);
    __half *xq, *xv, *ao, *wq, *wv, *wo;
    cudaGetSymbolAddress((void**)&xq, g_xq);
    cudaGetSymbolAddress((void**)&xv, g_xv);
    cudaGetSymbolAddress((void**)&ao, g_ao);
    cudaGetSymbolAddress((void**)&wq, g_wqk);
    cudaGetSymbolAddress((void**)&wv, g_wv);
    cudaGetSymbolAddress((void**)&wo, g_wo);

    cudaFuncSetAttribute(gemm_tc<true, true>,
                         cudaFuncAttributeMaxDynamicSharedMemorySize, GEMM_SMEM);
    cudaFuncSetAttribute(gemm_tc<false, false>,
                         cudaFuncAttributeMaxDynamicSharedMemorySize, GEMM_SMEM);
    cudaFuncSetAttribute(gemm_v_kv,
                         cudaFuncAttributeMaxDynamicSharedMemorySize, GEMM_SMEM);
    cudaFuncSetAttribute(attn_tc_kernel,
                         cudaFuncAttributeMaxDynamicSharedMemorySize, ATTN_SMEM);

    // Staggered fork-join pipeline across 4 batch groups.
    // Handles created ONCE per process (avoids stream-pool growth inside the
    // capture-window mem checkpoint, which failed R10). Staircase skew: group
    // g+1's conv_xt waits on group g's conv_xt event, so memory phases of one
    // group overlap tensor phases of the others (R11 ran chains in lockstep).
    static cudaStream_t s_st[NGRP - 1];
    static cudaEvent_t  s_evRoot;                // weights ready
    static cudaEvent_t  s_evXt[NGRP];            // conv_xt done per group
    static cudaEvent_t  s_evDone[NGRP - 1];
    static bool s_init = false;
    if (!s_init) {
        for (int g = 0; g < NGRP - 1; g++)
            cudaStreamCreateWithFlags(&s_st[g], cudaStreamNonBlocking);
        cudaEventCreateWithFlags(&s_evRoot, cudaEventDisableTiming);
        for (int g = 0; g < NGRP; g++)
            cudaEventCreateWithFlags(&s_evXt[g], cudaEventDisableTiming);
        for (int g = 0; g < NGRP - 1; g++)
            cudaEventCreateWithFlags(&s_evDone[g], cudaEventDisableTiming);
        s_init = true;
    }

    // 0) weight converts on origin stream (only GEMMs depend on this)
    conv_w_all<<<4096, 256>>>(w_qk, w_v, w_o, wq, wv, wo);
    cudaEventRecord(s_evRoot, 0);

    auto tail = [&](int g, cudaStream_t stm) {     // everything after conv_xt
        const int bz0 = g * GB;
        const int bh0 = bz0 * NH;
        gemm_tc<true, true><<<dim3(NN / 128, 1024 / 128, GB), 128, GEMM_SMEM, stm>>>(
            wq, xq, qk, 1024, bz0);
        gemm_v_kv<<<dim3(NN / 128, 512 / 128, GB), 128, GEMM_SMEM, stm>>>(
            wv, xv, qk, kvp, bz0);
        kv_reduce<<<(GB * 8 * 4160 + 255) / 256, 256, 0, stm>>>(kvp, kvr, bh0);
        attn_tc_kernel<<<dim3(NN / 128, GB * 8), 128, ATTN_SMEM, stm>>>(
            qk, kvr, ao, bh0);
        gemm_tc<false, false><<<dim3(NN / 128, 512 / 128, GB), 128, GEMM_SMEM, stm>>>(
            wo, ao, out, 512, bz0);
    };

    // group 0: conv_xt on origin (runs right after conv_w_all; conv_xt doesn't
    // need weights, and conv_w is tiny), then the GEMM tail.
    conv_xt_kernel<<<dim3(NN / 64, CC / 64, GB), 256, 0, (cudaStream_t)0>>>(
        x, pos, xq, xv, 0);
    cudaEventRecord(s_evXt[0], 0);
    tail(0, (cudaStream_t)0);

    // groups 1..3: conv_xt staggered after previous group's conv_xt; GEMMs
    // additionally gated on the weights event.
    for (int g = 1; g < NGRP; g++) {
        cudaStream_t stm = s_st[g - 1];
        cudaStreamWaitEvent(stm, s_evXt[g - 1], 0);
        conv_xt_kernel<<<dim3(NN / 64, CC / 64, GB), 256, 0, stm>>>(
            x, pos, xq, xv, g * GB);
        cudaEventRecord(s_evXt[g], stm);
        cudaStreamWaitEvent(stm, s_evRoot, 0);
        tail(g, stm);
        cudaEventRecord(s_evDone[g - 1], stm);
    }

    // join all branches back to the origin stream
    for (int g = 0; g < NGRP - 1; g++)
        cudaStreamWaitEvent(0, s_evDone[g], 0);
}

// round 14
// speedup vs baseline: 1.0034x; 1.0034x over previous
#include <cuda_runtime.h>
#include <cuda_fp16.h>
#include <cstdint>
#include <cstddef>

// Problem constants
#define BB   16
#define CC   512
#define NN   4096
#define NH   8
#define HD   64
#define EPS  1e-6f
#define NGRP 4
#define GB   (BB / NGRP)   // batches per group = 4

// ---------------------------------------------------------------------------
// Scratch (device globals: allocation-free rule)
// ---------------------------------------------------------------------------
__device__ __half g_qkh[(size_t)BB * 2 * CC * NN]; // [B][1024][4096] relu(qk) fp16
__device__ float g_kvp[(size_t)32 * 128 * 65 * 64];// split-K partials (32 chunks)
__device__ float g_kv [(size_t)128 * 65 * 64];     // [B*nh][65][64] fp32

// fp16 activations, [B][N][C] K-major
__device__ __half g_xq[(size_t)BB * NN * CC];      // x + pos
__device__ __half g_xv[(size_t)BB * NN * CC];      // x
__device__ __half g_ao[(size_t)BB * NN * CC];      // attn output (transposed)
// weights fp16, [O][C] K-major
__device__ __half g_wqk[1024 * 512];
__device__ __half g_wv [512 * 512];
__device__ __half g_wo [512 * 512];

// ---------------------------------------------------------------------------
// Helpers
// ---------------------------------------------------------------------------
__device__ __forceinline__ uint32_t smem_u32(const void* p) {
    uint32_t a;
    asm("{ .reg .u64 t; cvta.to.shared.u64 t, %1; cvt.u32.u64 %0, t; }" : "=r"(a) : "l"(p));
    return a;
}
#define SWZ128(off) ((off) ^ (((off) >> 3) & 0x70))
#define ONES2 0x3C003C00u

__device__ __forceinline__ void cp_async16(uint32_t s, const void* g) {
    asm volatile("cp.async.cg.shared.global [%0], [%1], 16;" :: "r"(s), "l"(g));
}
#define CP_COMMIT() asm volatile("cp.async.commit_group;" ::: "memory")
#define CP_WAIT(n)  asm volatile("cp.async.wait_group %0;" :: "n"(n) : "memory")

__device__ __forceinline__ void ldmatrix_x4(uint32_t* r, uint32_t addr) {
    asm volatile("ldmatrix.sync.aligned.m8n8.x4.shared.b16 {%0,%1,%2,%3}, [%4];"
                 : "=r"(r[0]), "=r"(r[1]), "=r"(r[2]), "=r"(r[3]) : "r"(addr));
}
__device__ __forceinline__ void mma_f16(float* d, const uint32_t* a, const uint32_t* b) {
    asm volatile(
        "mma.sync.aligned.m16n8k16.row.col.f32.f16.f16.f32 "
        "{%0,%1,%2,%3}, {%4,%5,%6,%7}, {%8,%9}, {%0,%1,%2,%3};"
        : "+f"(d[0]), "+f"(d[1]), "+f"(d[2]), "+f"(d[3])
        : "r"(a[0]), "r"(a[1]), "r"(a[2]), "r"(a[3]), "r"(b[0]), "r"(b[1]));
}

// 128-thread GEMM config: BM=128, BN=128, BK=64, warp tile 64x64, 3 stages.
#define BKB 128
#define B_OFF  16384
#define STG    32768
#define GEMM_SMEM (3 * STG)

// ---------------------------------------------------------------------------
// qk / o projection GEMM:  Y[O,N] = W[O,C] @ X[C,N]  (batches bz0 + blockIdx.z)
// Prefetch-first mainloop: stage it+2 issued BEFORE compute so the DMA hides
// under the mma chain (stage (it+2)%3 was released by the barrier of it-1).
// ---------------------------------------------------------------------------
template<bool RELU, bool HOUT>
__global__ __launch_bounds__(128, 2) void gemm_tc(
    const __half* __restrict__ A, const __half* __restrict__ Bx,
    void* __restrict__ Yv, int O, int bz0)
{
    extern __shared__ __align__(1024) char smem[];
    const uint32_t sbase = smem_u32(smem);
    const int tid  = threadIdx.x;
    const int wid  = tid >> 5;
    const int lane = tid & 31;
    const int wm   = wid & 1;
    const int wn   = wid >> 1;

    const int n0 = blockIdx.x * 128;
    const int o0 = blockIdx.y * 128;
    const int bz = bz0 + blockIdx.z;

    const __half* Bb = Bx + (size_t)bz * NN * CC;

    auto load_stage = [&](int ck, int st) {
        const int k0 = ck * 64;
        const uint32_t sb = sbase + st * STG;
        #pragma unroll
        for (int i = 0; i < 8; i++) {
            int c = tid + i * 128;
            int row = c >> 3, cc = c & 7;
            cp_async16(sb + SWZ128((uint32_t)(row * BKB + cc * 16)),
                       A + (size_t)(o0 + row) * CC + k0 + cc * 8);
        }
        #pragma unroll
        for (int i = 0; i < 8; i++) {
            int c = tid + i * 128;
            int row = c >> 3, cc = c & 7;
            cp_async16(sb + B_OFF + SWZ128((uint32_t)(row * BKB + cc * 16)),
                       Bb + (size_t)(n0 + row) * CC + k0 + cc * 8);
        }
        CP_COMMIT();
    };

    float acc[4][8][4];
    #pragma unroll
    for (int mf = 0; mf < 4; mf++)
        #pragma unroll
        for (int nf = 0; nf < 8; nf++)
            #pragma unroll
            for (int e = 0; e < 4; e++) acc[mf][nf][e] = 0.f;

    load_stage(0, 0);
    load_stage(1, 1);
    CP_WAIT(1);
    __syncthreads();

    const int a_row  = wm * 64 + (lane & 15);
    const int a_coff = (lane >> 4) * 16;
    const int b_row  = wn * 64 + ((lane >> 4) << 3) + (lane & 7);
    const int b_coff = ((lane >> 3) & 1) * 16;

    for (int it = 0; it < 8; it++) {
        if (it + 2 < 8) load_stage(it + 2, (it + 2) % 3);   // prefetch first
        const uint32_t sb = sbase + (it % 3) * STG;
        #pragma unroll
        for (int kk = 0; kk < 4; kk++) {
            uint32_t a[4][4], b[8][2];
            #pragma unroll
            for (int mf = 0; mf < 4; mf++)
                ldmatrix_x4(a[mf], sb +
                            SWZ128((uint32_t)((a_row + mf * 16) * BKB + kk * 32 + a_coff)));
            #pragma unroll
            for (int ng = 0; ng < 4; ng++) {
                uint32_t r[4];
                ldmatrix_x4(r, sb + B_OFF +
                            SWZ128((uint32_t)((b_row + ng * 16) * BKB + kk * 32 + b_coff)));
                b[ng * 2][0] = r[0];  b[ng * 2][1] = r[1];
                b[ng * 2 + 1][0] = r[2];  b[ng * 2 + 1][1] = r[3];
            }
            #pragma unroll
            for (int mf = 0; mf < 4; mf++)
                #pragma unroll
                for (int nf = 0; nf < 8; nf++)
                    mma_f16(acc[mf][nf], a[mf], b[nf]);
        }
        if (it + 2 < 8) { CP_WAIT(1); } else { CP_WAIT(0); }
        __syncthreads();
    }

    const int er = lane >> 2;
    const int ec = (lane & 3) * 2;
    #pragma unroll
    for (int mf = 0; mf < 4; mf++) {
        #pragma unroll
        for (int nf = 0; nf < 8; nf++) {
            const int orow = o0 + wm * 64 + mf * 16 + er;
            const int ocol = n0 + wn * 64 + nf * 8 + ec;
            float v0x = acc[mf][nf][0], v0y = acc[mf][nf][1];
            float v1x = acc[mf][nf][2], v1y = acc[mf][nf][3];
            if (RELU) {
                v0x = fmaxf(v0x, 0.f); v0y = fmaxf(v0y, 0.f);
                v1x = fmaxf(v1x, 0.f); v1y = fmaxf(v1y, 0.f);
            }
            if (HOUT) {
                __half* Yb = (__half*)Yv + (size_t)bz * O * NN;
                *(__half2*)&Yb[(size_t)orow * NN + ocol] = __floats2half2_rn(v0x, v0y);
                *(__half2*)&Yb[(size_t)(orow + 8) * NN + ocol] = __floats2half2_rn(v1x, v1y);
            } else {
                float* Yb = (float*)Yv + (size_t)bz * O * NN;
                *(float2*)&Yb[(size_t)orow * NN + ocol]       = make_float2(v0x, v0y);
                *(float2*)&Yb[(size_t)(orow + 8) * NN + ocol] = make_float2(v1x, v1y);
            }
        }
    }
}

// ---------------------------------------------------------------------------
// Fused v-GEMM + kv (batches bz0 + blockIdx.z), prefetch-first mainloop.
// ---------------------------------------------------------------------------
#define VP 136
#define KV_KOFF 34816

__global__ __launch_bounds__(128, 2) void gemm_v_kv(
    const __half* __restrict__ A, const __half* __restrict__ Bx,
    const __half* __restrict__ qk, float* __restrict__ kvp, int bz0)
{
    extern __shared__ __align__(1024) char smem[];
    const uint32_t sbase = smem_u32(smem);
    const int tid  = threadIdx.x;
    const int wid  = tid >> 5;
    const int lane = tid & 31;
    const int wm   = wid & 1;
    const int wn   = wid >> 1;

    const int n0 = blockIdx.x * 128;
    const int o0 = blockIdx.y * 128;
    const int bz = bz0 + blockIdx.z;

    const __half* Bb = Bx + (size_t)bz * NN * CC;

    auto load_stage = [&](int ck, int st) {
        const int k0 = ck * 64;
        const uint32_t sb = sbase + st * STG;
        #pragma unroll
        for (int i = 0; i < 8; i++) {
            int c = tid + i * 128;
            int row = c >> 3, cc = c & 7;
            cp_async16(sb + SWZ128((uint32_t)(row * BKB + cc * 16)),
                       A + (size_t)(o0 + row) * CC + k0 + cc * 8);
        }
        #pragma unroll
        for (int i = 0; i < 8; i++) {
            int c = tid + i * 128;
            int row = c >> 3, cc = c & 7;
            cp_async16(sb + B_OFF + SWZ128((uint32_t)(row * BKB + cc * 16)),
                       Bb + (size_t)(n0 + row) * CC + k0 + cc * 8);
        }
        CP_COMMIT();
    };

    float acc[4][8][4];
    #pragma unroll
    for (int mf = 0; mf < 4; mf++)
        #pragma unroll
        for (int nf = 0; nf < 8; nf++)
            #pragma unroll
            for (int e = 0; e < 4; e++) acc[mf][nf][e] = 0.f;

    load_stage(0, 0);
    load_stage(1, 1);
    CP_WAIT(1);
    __syncthreads();

    const int a_row  = wm * 64 + (lane & 15);
    const int a_coff = (lane >> 4) * 16;
    const int b_row  = wn * 64 + ((lane >> 4) << 3) + (lane & 7);
    const int b_coff = ((lane >> 3) & 1) * 16;

    for (int it = 0; it < 8; it++) {
        if (it + 2 < 8) load_stage(it + 2, (it + 2) % 3);   // prefetch first
        const uint32_t sb = sbase + (it % 3) * STG;
        #pragma unroll
        for (int kk = 0; kk < 4; kk++) {
            uint32_t a[4][4], b[8][2];
            #pragma unroll
            for (int mf = 0; mf < 4; mf++)
                ldmatrix_x4(a[mf], sb +
                            SWZ128((uint32_t)((a_row + mf * 16) * BKB + kk * 32 + a_coff)));
            #pragma unroll
            for (int ng = 0; ng < 4; ng++) {
                uint32_t r[4];
                ldmatrix_x4(r, sb + B_OFF +
                            SWZ128((uint32_t)((b_row + ng * 16) * BKB + kk * 32 + b_coff)));
                b[ng * 2][0] = r[0];  b[ng * 2][1] = r[1];
                b[ng * 2 + 1][0] = r[2];  b[ng * 2 + 1][1] = r[3];
            }
            #pragma unroll
            for (int mf = 0; mf < 4; mf++)
                #pragma unroll
                for (int nf = 0; nf < 8; nf++)
                    mma_f16(acc[mf][nf], a[mf], b[nf]);
        }
        if (it + 2 < 8) { CP_WAIT(1); } else { CP_WAIT(0); }
        __syncthreads();
    }

    // ---- epilogue: v tile (fp16) -> smem [128][VP]; k tile -> smem ----
    __half* sv = (__half*)smem;
    const int er = lane >> 2;
    const int ec = (lane & 3) * 2;
    #pragma unroll
    for (int mf = 0; mf < 4; mf++) {
        #pragma unroll
        for (int nf = 0; nf < 8; nf++) {
            const int lr = wm * 64 + mf * 16 + er;
            const int lc = wn * 64 + nf * 8 + ec;
            *(__half2*)&sv[lr * VP + lc] =
                __floats2half2_rn(acc[mf][nf][0], acc[mf][nf][1]);
            *(__half2*)&sv[(lr + 8) * VP + lc] =
                __floats2half2_rn(acc[mf][nf][2], acc[mf][nf][3]);
        }
    }
    const __half* kb = qk + ((size_t)bz * 2 * CC + CC + o0) * NN + n0;
    #pragma unroll
    for (int i = 0; i < 16; i++) {
        int idx = tid + i * 128;
        int r = idx >> 4, c = idx & 15;
        cp_async16(sbase + KV_KOFF + (uint32_t)(r * 272 + c * 16),
                   kb + (size_t)r * NN + c * 8);
    }
    CP_COMMIT();
    CP_WAIT(0);
    __syncthreads();

    const int dgrp = wid;
    const int arow2 = lane & 15;
    const int acoff2 = (lane >> 4) * 16;
    const int bcoff2 = ((lane >> 3) & 1) * 16;
    const uint32_t ones[4] = {ONES2, ONES2, ONES2, ONES2};

    for (int head = 0; head < 2; head++) {
        float kacc[5][2][4];
        #pragma unroll
        for (int m = 0; m < 5; m++)
            #pragma unroll
            for (int nt = 0; nt < 2; nt++)
                #pragma unroll
                for (int e = 0; e < 4; e++) kacc[m][nt][e] = 0.f;

        const int brow2 = head * 64 + dgrp * 16 + ((lane >> 4) << 3) + (lane & 7);
        #pragma unroll
        for (int ks = 0; ks < 8; ks++) {
            uint32_t bf[4];
            ldmatrix_x4(bf, sbase + KV_KOFF + (uint32_t)(brow2 * 272 + ks * 32 + bcoff2));
            uint32_t b0[2] = {bf[0], bf[1]}, b1[2] = {bf[2], bf[3]};
            #pragma unroll
            for (int m = 0; m < 4; m++) {
                uint32_t a[4];
                ldmatrix_x4(a, sbase +
                            (uint32_t)((head * 64 + m * 16 + arow2) * 272 + ks * 32 + acoff2));
                mma_f16(kacc[m][0], a, b0);
                mma_f16(kacc[m][1], a, b1);
            }
            mma_f16(kacc[4][0], ones, b0);
            mma_f16(kacc[4][1], ones, b1);
        }

        const int bh = bz * 8 + blockIdx.y * 2 + head;
        float* outb = kvp + (size_t)blockIdx.x * (128 * 4160) + (size_t)bh * 4160;
        #pragma unroll
        for (int m = 0; m < 4; m++)
            #pragma unroll
            for (int nt = 0; nt < 2; nt++) {
                const int e = m * 16 + (lane >> 2);
                const int d = dgrp * 16 + nt * 8 + 2 * (lane & 3);
                *(float2*)&outb[e * 64 + d]       = make_float2(kacc[m][nt][0], kacc[m][nt][1]);
                *(float2*)&outb[(e + 8) * 64 + d] = make_float2(kacc[m][nt][2], kacc[m][nt][3]);
            }
        if (lane < 4) {
            #pragma unroll
            for (int nt = 0; nt < 2; nt++) {
                const int d = dgrp * 16 + nt * 8 + 2 * lane;
                *(float2*)&outb[4096 + d] = make_float2(kacc[4][nt][0], kacc[4][nt][1]);
            }
        }
    }
}

// ---------------------------------------------------------------------------
// Weight convert (all three in one launch)
// ---------------------------------------------------------------------------
__global__ void conv_w_all(const float* __restrict__ wqk, const float* __restrict__ wv,
                           const float* __restrict__ wo,
                           __half* __restrict__ oq, __half* __restrict__ ov,
                           __half* __restrict__ oo)
{
    int i = blockIdx.x * 256 + threadIdx.x;
    if (i < 524288) {
        oq[i] = __float2half_rn(wqk[i]);
    } else if (i < 786432) {
        int j = i - 524288; ov[j] = __float2half_rn(wv[j]);
    } else if (i < 1048576) {
        int j = i - 786432; oo[j] = __float2half_rn(wo[j]);
    }
}

// ---------------------------------------------------------------------------
// Transpose + fp16 convert (batches bz0 + blockIdx.z)
// ---------------------------------------------------------------------------
__global__ __launch_bounds__(256) void conv_xt_kernel(
    const float* __restrict__ x, const float* __restrict__ pos,
    __half* __restrict__ xq, __half* __restrict__ xv, int bz0)
{
    __shared__ float sA[64][65];
    __shared__ float sB[64][65];

    const int tid = threadIdx.x;
    const int n0 = blockIdx.x * 64;
    const int c0 = blockIdx.y * 64;
    const int bz = bz0 + blockIdx.z;

    const float* i0 = x   + (size_t)bz * CC * NN;
    const float* i1 = pos + (size_t)bz * CC * NN;

    #pragma unroll
    for (int i = 0; i < 4; i++) {
        int idx = i * 256 + tid;
        int rc = idx >> 4, cn = (idx & 15) * 4;
        float4 xv4 = *(const float4*)&i0[(size_t)(c0 + rc) * NN + n0 + cn];
        float4 pv4 = *(const float4*)&i1[(size_t)(c0 + rc) * NN + n0 + cn];
        sA[rc][cn]     = xv4.x + pv4.x;
        sA[rc][cn + 1] = xv4.y + pv4.y;
        sA[rc][cn + 2] = xv4.z + pv4.z;
        sA[rc][cn + 3] = xv4.w + pv4.w;
        sB[rc][cn]     = xv4.x;
        sB[rc][cn + 1] = xv4.y;
        sB[rc][cn + 2] = xv4.z;
        sB[rc][cn + 3] = xv4.w;
    }
    __syncthreads();

    const size_t obase = ((size_t)bz * NN + n0) * CC + c0;
    #pragma unroll
    for (int i = 0; i < 8; i++) {
        int idx = i * 256 + tid;
        int nr = idx >> 5, cp = idx & 31;
        size_t oa = obase + (size_t)nr * CC + cp * 2;
        __half2 hq, hv;
        hq.x = __float2half_rn(sA[cp * 2][nr]);
        hq.y = __float2half_rn(sA[cp * 2 + 1][nr]);
        hv.x = __float2half_rn(sB[cp * 2][nr]);
        hv.y = __float2half_rn(sB[cp * 2 + 1][nr]);
        *(__half2*)(xq + oa) = hq;
        *(__half2*)(xv + oa) = hv;
    }
}

// ---------------------------------------------------------------------------
// kv reduce for one group of bh (32 bh per group)
// ---------------------------------------------------------------------------
__global__ void kv_reduce(const float* __restrict__ kvp, float* __restrict__ kvout,
                          int bh0)
{
    int i = blockIdx.x * 256 + threadIdx.x;
    if (i < GB * 8 * 4160) {
        size_t j = (size_t)bh0 * 4160 + i;
        float s = 0.f;
        #pragma unroll
        for (int c = 0; c < 32; c++) s += kvp[(size_t)c * (128 * 4160) + j];
        kvout[j] = s;
    }
}

// ---------------------------------------------------------------------------
// attn (tensor cores): out[e,n] = (kv @ q)[e,n] / (ksum@q[n] + EPS)
// ---------------------------------------------------------------------------
#define AT_AH 0
#define AT_AL 10240
#define AT_B  20480
#define AT_SCR 36864
#define ATTN_SMEM 55296

__global__ __launch_bounds__(128) void attn_tc_kernel(
    const __half* __restrict__ qk, const float* __restrict__ kv,
    __half* __restrict__ ao, int bh0)
{
    extern __shared__ __align__(1024) char smem[];
    const uint32_t sbase = smem_u32(smem);
    __half* S1   = (__half*)(smem + AT_SCR);
    __half* sOut = (__half*)(smem + AT_SCR);

    const int tid  = threadIdx.x;
    const int wid  = tid >> 5;
    const int lane = tid & 31;
    const int bh   = bh0 + blockIdx.y;
    const int b = bh >> 3, h = bh & 7;
    const int n0 = blockIdx.x * 128;

    const __half* qbase = qk + ((size_t)b * 2 * CC + h * HD) * NN + n0;
    #pragma unroll
    for (int i = 0; i < 8; i++) {
        int idx = tid + i * 128;
        int d = idx >> 4, j = idx & 15;
        cp_async16(sbase + AT_SCR + (uint32_t)(d * 288 + j * 16),
                   qbase + (size_t)d * NN + j * 8);
    }
    CP_COMMIT();

    {
        uint4 z = {0, 0, 0, 0};
        for (int i = tid; i < 1280; i += 128)
            *(uint4*)(smem + AT_AH + i * 16) = z;
    }
    __syncthreads();
    const float* kvb = kv + (size_t)bh * 4160;
    for (int i = tid; i < 4160; i += 128) {
        int e = i >> 6, d = i & 63;
        float f = kvb[i];
        __half hi = __float2half_rn(f);
        __half lo = __float2half_rn(f - __half2float(hi));
        uint32_t off = SWZ128((uint32_t)(e * 128 + d * 2));
        *(__half*)(smem + AT_AH + off) = hi;
        *(__half*)(smem + AT_AL + off) = lo;
    }
    CP_WAIT(0);
    __syncthreads();

    {
        union { __half hh[8]; uint4 u; } pk;
        const int n = tid;
        #pragma unroll
        for (int j = 0; j < 8; j++) {
            #pragma unroll
            for (int d2 = 0; d2 < 8; d2++)
                pk.hh[d2] = S1[(j * 8 + d2) * 144 + n];
            *(uint4*)(smem + AT_B + SWZ128((uint32_t)(n * 128 + j * 16))) = pk.u;
        }
    }
    __syncthreads();

    float acc[5][4][4];
    #pragma unroll
    for (int m = 0; m < 5; m++)
        #pragma unroll
        for (int nt = 0; nt < 4; nt++)
            #pragma unroll
            for (int e = 0; e < 4; e++) acc[m][nt][e] = 0.f;

    const int a_row  = lane & 15;
    const int a_coff = (lane >> 4) * 16;
    const int b_coff = ((lane >> 3) & 1) * 16;

    #pragma unroll
    for (int ks = 0; ks < 4; ks++) {
        uint32_t ah[5][4], al[5][4], bfr[4][2];
        #pragma unroll
        for (int m = 0; m < 5; m++) {
            const uint32_t so = SWZ128((uint32_t)((m * 16 + a_row) * 128 + ks * 32 + a_coff));
            ldmatrix_x4(ah[m], sbase + AT_AH + so);
            ldmatrix_x4(al[m], sbase + AT_AL + so);
        }
        #pragma unroll
        for (int g = 0; g < 2; g++) {
            const int brow = wid * 32 + g * 16 + ((lane >> 4) << 3) + (lane & 7);
            uint32_t r[4];
            ldmatrix_x4(r, sbase + AT_B + SWZ128((uint32_t)(brow * 128 + ks * 32 + b_coff)));
            bfr[g * 2][0] = r[0];  bfr[g * 2][1] = r[1];
            bfr[g * 2 + 1][0] = r[2];  bfr[g * 2 + 1][1] = r[3];
        }
        #pragma unroll
        for (int m = 0; m < 5; m++)
            #pragma unroll
            for (int nt = 0; nt < 4; nt++) {
                mma_f16(acc[m][nt], ah[m], bfr[nt]);
                mma_f16(acc[m][nt], al[m], bfr[nt]);
            }
    }

    #pragma unroll
    for (int nt = 0; nt < 4; nt++) {
        float den0 = __shfl_sync(0xffffffffu, acc[4][nt][0], lane & 3);
        float den1 = __shfl_sync(0xffffffffu, acc[4][nt][1], lane & 3);
        float inv0 = 1.f / (den0 + EPS);
        float inv1 = 1.f / (den1 + EPS);
        const int n = wid * 32 + nt * 8 + 2 * (lane & 3);
        #pragma unroll
        for (int m = 0; m < 4; m++) {
            const int e = m * 16 + (lane >> 2);
            sOut[n * 72 + e]           = __float2half_rn(acc[m][nt][0] * inv0);
            sOut[(n + 1) * 72 + e]     = __float2half_rn(acc[m][nt][1] * inv1);
            sOut[n * 72 + e + 8]       = __float2half_rn(acc[m][nt][2] * inv0);
            sOut[(n + 1) * 72 + e + 8] = __float2half_rn(acc[m][nt][3] * inv1);
        }
    }
    __syncthreads();

    {
        const int n = tid;
        __half* dst = ao + ((size_t)b * NN + n0 + n) * CC + h * HD;
        #pragma unroll
        for (int j = 0; j < 8; j++)
            *(uint4*)(dst + j * 8) = *(uint4*)(sOut + n * 72 + j * 8);
    }
}

// ---------------------------------------------------------------------------
extern "C" void kernel_launch(void* const* d_in, const int* in_sizes, int n_in,
                              void* d_out, int out_size)
{
    const float* x    = (const float*)d_in[0];
    const float* pos  = (const float*)d_in[1];
    const float* w_qk = (const float*)d_in[2];
    const float* w_v  = (const float*)d_in[3];
    const float* w_o  = (const float*)d_in[4];
    float* out = (float*)d_out;

    __half *qk;
    float *kvp, *kvr;
    cudaGetSymbolAddress((void**)&qk,  g_qkh);
    cudaGetSymbolAddress((void**)&kvp, g_kvp);
    cudaGetSymbolAddress((void**)&kvr, g_kv);
    __half *xq, *xv, *ao, *wq, *wv, *wo;
    cudaGetSymbolAddress((void**)&xq, g_xq);
    cudaGetSymbolAddress((void**)&xv, g_xv);
    cudaGetSymbolAddress((void**)&ao, g_ao);
    cudaGetSymbolAddress((void**)&wq, g_wqk);
    cudaGetSymbolAddress((void**)&wv, g_wv);
    cudaGetSymbolAddress((void**)&wo, g_wo);

    cudaFuncSetAttribute(gemm_tc<true, true>,
                         cudaFuncAttributeMaxDynamicSharedMemorySize, GEMM_SMEM);
    cudaFuncSetAttribute(gemm_tc<false, false>,
                         cudaFuncAttributeMaxDynamicSharedMemorySize, GEMM_SMEM);
    cudaFuncSetAttribute(gemm_v_kv,
                         cudaFuncAttributeMaxDynamicSharedMemorySize, GEMM_SMEM);
    cudaFuncSetAttribute(attn_tc_kernel,
                         cudaFuncAttributeMaxDynamicSharedMemorySize, ATTN_SMEM);

    // R11 orchestration (proven clean on all mem checkpoints): 3 forked
    // streams + origin, phase-concurrent groups. Handles created once.
    static cudaStream_t s_st[NGRP - 1];
    static cudaEvent_t  s_evRoot;
    static cudaEvent_t  s_evDone[NGRP - 1];
    static bool s_init = false;
    if (!s_init) {
        for (int g = 0; g < NGRP - 1; g++)
            cudaStreamCreateWithFlags(&s_st[g], cudaStreamNonBlocking);
        cudaEventCreateWithFlags(&s_evRoot, cudaEventDisableTiming);
        for (int g = 0; g < NGRP - 1; g++)
            cudaEventCreateWithFlags(&s_evDone[g], cudaEventDisableTiming);
        s_init = true;
    }

    // 0) weight converts on origin stream
    conv_w_all<<<4096, 256>>>(w_qk, w_v, w_o, wq, wv, wo);
    cudaEventRecord(s_evRoot, 0);

    auto chain = [&](int g, cudaStream_t stm) {
        const int bz0 = g * GB;
        const int bh0 = bz0 * NH;

        conv_xt_kernel<<<dim3(NN / 64, CC / 64, GB), 256, 0, stm>>>(
            x, pos, xq, xv, bz0);
        gemm_tc<true, true><<<dim3(NN / 128, 1024 / 128, GB), 128, GEMM_SMEM, stm>>>(
            wq, xq, qk, 1024, bz0);
        gemm_v_kv<<<dim3(NN / 128, 512 / 128, GB), 128, GEMM_SMEM, stm>>>(
            wv, xv, qk, kvp, bz0);
        kv_reduce<<<(GB * 8 * 4160 + 255) / 256, 256, 0, stm>>>(kvp, kvr, bh0);
        attn_tc_kernel<<<dim3(NN / 128, GB * 8), 128, ATTN_SMEM, stm>>>(
            qk, kvr, ao, bh0);
        gemm_tc<false, false><<<dim3(NN / 128, 512 / 128, GB), 128, GEMM_SMEM, stm>>>(
            wo, ao, out, 512, bz0);
    };

    // group 0 on the origin stream (ordered after conv_w_all implicitly)
    chain(0, (cudaStream_t)0);

    // groups 1..3 on forked streams
    for (int g = 1; g < NGRP; g++) {
        cudaStreamWaitEvent(s_st[g - 1], s_evRoot, 0);
        chain(g, s_st[g - 1]);
        cudaEventRecord(s_evDone[g - 1], s_st[g - 1]);
    }

    // join all branches back to the origin stream
    for (int g = 0; g < NGRP - 1; g++)
        cudaStreamWaitEvent(0, s_evDone[g], 0);
}

// round 15
// speedup vs baseline: 1.0342x; 1.0307x over previous
#include <cuda_runtime.h>
#include <cuda_fp16.h>
#include <cstdint>
#include <cstddef>

// Problem constants
#define BB   16
#define CC   512
#define NN   4096
#define NH   8
#define HD   64
#define EPS  1e-6f
#define NGRP 4
#define GB   (BB / NGRP)   // batches per group = 4

// ---------------------------------------------------------------------------
// Scratch (device globals: allocation-free rule)
// ---------------------------------------------------------------------------
__device__ __half g_qkh[(size_t)BB * 2 * CC * NN]; // [B][1024][4096] relu(qk) fp16
__device__ float g_kvp[(size_t)32 * 128 * 65 * 64];// split-K partials (32 chunks)
__device__ float g_kv [(size_t)128 * 65 * 64];     // [B*nh][65][64] fp32

// fp16 activations, [B][N][C] K-major
__device__ __half g_xq[(size_t)BB * NN * CC];      // x + pos
__device__ __half g_xv[(size_t)BB * NN * CC];      // x
__device__ __half g_ao[(size_t)BB * NN * CC];      // attn output (transposed)
// weights fp16, [O][C] K-major
__device__ __half g_wqk[1024 * 512];
__device__ __half g_wv [512 * 512];
__device__ __half g_wo [512 * 512];

// ---------------------------------------------------------------------------
// Helpers
// ---------------------------------------------------------------------------
__device__ __forceinline__ uint32_t smem_u32(const void* p) {
    uint32_t a;
    asm("{ .reg .u64 t; cvta.to.shared.u64 t, %1; cvt.u32.u64 %0, t; }" : "=r"(a) : "l"(p));
    return a;
}
#define SWZ128(off) ((off) ^ (((off) >> 3) & 0x70))
#define ONES2 0x3C003C00u

__device__ __forceinline__ void cp_async16(uint32_t s, const void* g) {
    asm volatile("cp.async.cg.shared.global [%0], [%1], 16;" :: "r"(s), "l"(g));
}
#define CP_COMMIT() asm volatile("cp.async.commit_group;" ::: "memory")
#define CP_WAIT(n)  asm volatile("cp.async.wait_group %0;" :: "n"(n) : "memory")

__device__ __forceinline__ void ldmatrix_x4(uint32_t* r, uint32_t addr) {
    asm volatile("ldmatrix.sync.aligned.m8n8.x4.shared.b16 {%0,%1,%2,%3}, [%4];"
                 : "=r"(r[0]), "=r"(r[1]), "=r"(r[2]), "=r"(r[3]) : "r"(addr));
}
__device__ __forceinline__ void mma_f16(float* d, const uint32_t* a, const uint32_t* b) {
    asm volatile(
        "mma.sync.aligned.m16n8k16.row.col.f32.f16.f16.f32 "
        "{%0,%1,%2,%3}, {%4,%5,%6,%7}, {%8,%9}, {%0,%1,%2,%3};"
        : "+f"(d[0]), "+f"(d[1]), "+f"(d[2]), "+f"(d[3])
        : "r"(a[0]), "r"(a[1]), "r"(a[2]), "r"(a[3]), "r"(b[0]), "r"(b[1]));
}

// 128-thread GEMM config: BM=128, BN=128, BK=64, warp tile 64x64, 3 stages.
#define BKB 128
#define B_OFF  16384
#define STG    32768
#define GEMM_SMEM (3 * STG)

// ---------------------------------------------------------------------------
// qk / o projection GEMM:  Y[O,N] = W[O,C] @ X[C,N]  (batches bz0 + blockIdx.z)
// ---------------------------------------------------------------------------
template<bool RELU, bool HOUT>
__global__ __launch_bounds__(128, 2) void gemm_tc(
    const __half* __restrict__ A, const __half* __restrict__ Bx,
    void* __restrict__ Yv, int O, int bz0)
{
    extern __shared__ __align__(1024) char smem[];
    const uint32_t sbase = smem_u32(smem);
    const int tid  = threadIdx.x;
    const int wid  = tid >> 5;
    const int lane = tid & 31;
    const int wm   = wid & 1;
    const int wn   = wid >> 1;

    const int n0 = blockIdx.x * 128;
    const int o0 = blockIdx.y * 128;
    const int bz = bz0 + blockIdx.z;

    const __half* Bb = Bx + (size_t)bz * NN * CC;

    auto load_stage = [&](int ck, int st) {
        const int k0 = ck * 64;
        const uint32_t sb = sbase + st * STG;
        #pragma unroll
        for (int i = 0; i < 8; i++) {
            int c = tid + i * 128;
            int row = c >> 3, cc = c & 7;
            cp_async16(sb + SWZ128((uint32_t)(row * BKB + cc * 16)),
                       A + (size_t)(o0 + row) * CC + k0 + cc * 8);
        }
        #pragma unroll
        for (int i = 0; i < 8; i++) {
            int c = tid + i * 128;
            int row = c >> 3, cc = c & 7;
            cp_async16(sb + B_OFF + SWZ128((uint32_t)(row * BKB + cc * 16)),
                       Bb + (size_t)(n0 + row) * CC + k0 + cc * 8);
        }
        CP_COMMIT();
    };

    float acc[4][8][4];
    #pragma unroll
    for (int mf = 0; mf < 4; mf++)
        #pragma unroll
        for (int nf = 0; nf < 8; nf++)
            #pragma unroll
            for (int e = 0; e < 4; e++) acc[mf][nf][e] = 0.f;

    load_stage(0, 0);
    load_stage(1, 1);
    CP_WAIT(1);
    __syncthreads();

    const int a_row  = wm * 64 + (lane & 15);
    const int a_coff = (lane >> 4) * 16;
    const int b_row  = wn * 64 + ((lane >> 4) << 3) + (lane & 7);
    const int b_coff = ((lane >> 3) & 1) * 16;

    for (int it = 0; it < 8; it++) {
        const uint32_t sb = sbase + (it % 3) * STG;
        #pragma unroll
        for (int kk = 0; kk < 4; kk++) {
            uint32_t a[4][4], b[8][2];
            #pragma unroll
            for (int mf = 0; mf < 4; mf++)
                ldmatrix_x4(a[mf], sb +
                            SWZ128((uint32_t)((a_row + mf * 16) * BKB + kk * 32 + a_coff)));
            #pragma unroll
            for (int ng = 0; ng < 4; ng++) {
                uint32_t r[4];
                ldmatrix_x4(r, sb + B_OFF +
                            SWZ128((uint32_t)((b_row + ng * 16) * BKB + kk * 32 + b_coff)));
                b[ng * 2][0] = r[0];  b[ng * 2][1] = r[1];
                b[ng * 2 + 1][0] = r[2];  b[ng * 2 + 1][1] = r[3];
            }
            #pragma unroll
            for (int mf = 0; mf < 4; mf++)
                #pragma unroll
                for (int nf = 0; nf < 8; nf++)
                    mma_f16(acc[mf][nf], a[mf], b[nf]);
        }
        if (it + 2 < 8) {
            load_stage(it + 2, (it + 2) % 3);
            CP_WAIT(1);
        } else {
            CP_WAIT(0);
        }
        __syncthreads();
    }

    const int er = lane >> 2;
    const int ec = (lane & 3) * 2;
    #pragma unroll
    for (int mf = 0; mf < 4; mf++) {
        #pragma unroll
        for (int nf = 0; nf < 8; nf++) {
            const int orow = o0 + wm * 64 + mf * 16 + er;
            const int ocol = n0 + wn * 64 + nf * 8 + ec;
            float v0x = acc[mf][nf][0], v0y = acc[mf][nf][1];
            float v1x = acc[mf][nf][2], v1y = acc[mf][nf][3];
            if (RELU) {
                v0x = fmaxf(v0x, 0.f); v0y = fmaxf(v0y, 0.f);
                v1x = fmaxf(v1x, 0.f); v1y = fmaxf(v1y, 0.f);
            }
            if (HOUT) {
                __half* Yb = (__half*)Yv + (size_t)bz * O * NN;
                *(__half2*)&Yb[(size_t)orow * NN + ocol] = __floats2half2_rn(v0x, v0y);
                *(__half2*)&Yb[(size_t)(orow + 8) * NN + ocol] = __floats2half2_rn(v1x, v1y);
            } else {
                float* Yb = (float*)Yv + (size_t)bz * O * NN;
                *(float2*)&Yb[(size_t)orow * NN + ocol]       = make_float2(v0x, v0y);
                *(float2*)&Yb[(size_t)(orow + 8) * NN + ocol] = make_float2(v1x, v1y);
            }
        }
    }
}

// ---------------------------------------------------------------------------
// Fused v-GEMM + kv (batches bz0 + blockIdx.z)
// ---------------------------------------------------------------------------
#define VP 136
#define KV_KOFF 34816

__global__ __launch_bounds__(128, 2) void gemm_v_kv(
    const __half* __restrict__ A, const __half* __restrict__ Bx,
    const __half* __restrict__ qk, float* __restrict__ kvp, int bz0)
{
    extern __shared__ __align__(1024) char smem[];
    const uint32_t sbase = smem_u32(smem);
    const int tid  = threadIdx.x;
    const int wid  = tid >> 5;
    const int lane = tid & 31;
    const int wm   = wid & 1;
    const int wn   = wid >> 1;

    const int n0 = blockIdx.x * 128;
    const int o0 = blockIdx.y * 128;
    const int bz = bz0 + blockIdx.z;

    const __half* Bb = Bx + (size_t)bz * NN * CC;

    auto load_stage = [&](int ck, int st) {
        const int k0 = ck * 64;
        const uint32_t sb = sbase + st * STG;
        #pragma unroll
        for (int i = 0; i < 8; i++) {
            int c = tid + i * 128;
            int row = c >> 3, cc = c & 7;
            cp_async16(sb + SWZ128((uint32_t)(row * BKB + cc * 16)),
                       A + (size_t)(o0 + row) * CC + k0 + cc * 8);
        }
        #pragma unroll
        for (int i = 0; i < 8; i++) {
            int c = tid + i * 128;
            int row = c >> 3, cc = c & 7;
            cp_async16(sb + B_OFF + SWZ128((uint32_t)(row * BKB + cc * 16)),
                       Bb + (size_t)(n0 + row) * CC + k0 + cc * 8);
        }
        CP_COMMIT();
    };

    float acc[4][8][4];
    #pragma unroll
    for (int mf = 0; mf < 4; mf++)
        #pragma unroll
        for (int nf = 0; nf < 8; nf++)
            #pragma unroll
            for (int e = 0; e < 4; e++) acc[mf][nf][e] = 0.f;

    load_stage(0, 0);
    load_stage(1, 1);
    CP_WAIT(1);
    __syncthreads();

    const int a_row  = wm * 64 + (lane & 15);
    const int a_coff = (lane >> 4) * 16;
    const int b_row  = wn * 64 + ((lane >> 4) << 3) + (lane & 7);
    const int b_coff = ((lane >> 3) & 1) * 16;

    for (int it = 0; it < 8; it++) {
        const uint32_t sb = sbase + (it % 3) * STG;
        #pragma unroll
        for (int kk = 0; kk < 4; kk++) {
            uint32_t a[4][4], b[8][2];
            #pragma unroll
            for (int mf = 0; mf < 4; mf++)
                ldmatrix_x4(a[mf], sb +
                            SWZ128((uint32_t)((a_row + mf * 16) * BKB + kk * 32 + a_coff)));
            #pragma unroll
            for (int ng = 0; ng < 4; ng++) {
                uint32_t r[4];
                ldmatrix_x4(r, sb + B_OFF +
                            SWZ128((uint32_t)((b_row + ng * 16) * BKB + kk * 32 + b_coff)));
                b[ng * 2][0] = r[0];  b[ng * 2][1] = r[1];
                b[ng * 2 + 1][0] = r[2];  b[ng * 2 + 1][1] = r[3];
            }
            #pragma unroll
            for (int mf = 0; mf < 4; mf++)
                #pragma unroll
                for (int nf = 0; nf < 8; nf++)
                    mma_f16(acc[mf][nf], a[mf], b[nf]);
        }
        if (it + 2 < 8) {
            load_stage(it + 2, (it + 2) % 3);
            CP_WAIT(1);
        } else {
            CP_WAIT(0);
        }
        __syncthreads();
    }

    // ---- epilogue: v tile (fp16) -> smem [128][VP]; k tile -> smem ----
    __half* sv = (__half*)smem;
    const int er = lane >> 2;
    const int ec = (lane & 3) * 2;
    #pragma unroll
    for (int mf = 0; mf < 4; mf++) {
        #pragma unroll
        for (int nf = 0; nf < 8; nf++) {
            const int lr = wm * 64 + mf * 16 + er;
            const int lc = wn * 64 + nf * 8 + ec;
            *(__half2*)&sv[lr * VP + lc] =
                __floats2half2_rn(acc[mf][nf][0], acc[mf][nf][1]);
            *(__half2*)&sv[(lr + 8) * VP + lc] =
                __floats2half2_rn(acc[mf][nf][2], acc[mf][nf][3]);
        }
    }
    const __half* kb = qk + ((size_t)bz * 2 * CC + CC + o0) * NN + n0;
    #pragma unroll
    for (int i = 0; i < 16; i++) {
        int idx = tid + i * 128;
        int r = idx >> 4, c = idx & 15;
        cp_async16(sbase + KV_KOFF + (uint32_t)(r * 272 + c * 16),
                   kb + (size_t)r * NN + c * 8);
    }
    CP_COMMIT();
    CP_WAIT(0);
    __syncthreads();

    const int dgrp = wid;
    const int arow2 = lane & 15;
    const int acoff2 = (lane >> 4) * 16;
    const int bcoff2 = ((lane >> 3) & 1) * 16;
    const uint32_t ones[4] = {ONES2, ONES2, ONES2, ONES2};

    for (int head = 0; head < 2; head++) {
        float kacc[5][2][4];
        #pragma unroll
        for (int m = 0; m < 5; m++)
            #pragma unroll
            for (int nt = 0; nt < 2; nt++)
                #pragma unroll
                for (int e = 0; e < 4; e++) kacc[m][nt][e] = 0.f;

        const int brow2 = head * 64 + dgrp * 16 + ((lane >> 4) << 3) + (lane & 7);
        #pragma unroll
        for (int ks = 0; ks < 8; ks++) {
            uint32_t bf[4];
            ldmatrix_x4(bf, sbase + KV_KOFF + (uint32_t)(brow2 * 272 + ks * 32 + bcoff2));
            uint32_t b0[2] = {bf[0], bf[1]}, b1[2] = {bf[2], bf[3]};
            #pragma unroll
            for (int m = 0; m < 4; m++) {
                uint32_t a[4];
                ldmatrix_x4(a, sbase +
                            (uint32_t)((head * 64 + m * 16 + arow2) * 272 + ks * 32 + acoff2));
                mma_f16(kacc[m][0], a, b0);
                mma_f16(kacc[m][1], a, b1);
            }
            mma_f16(kacc[4][0], ones, b0);
            mma_f16(kacc[4][1], ones, b1);
        }

        const int bh = bz * 8 + blockIdx.y * 2 + head;
        float* outb = kvp + (size_t)blockIdx.x * (128 * 4160) + (size_t)bh * 4160;
        #pragma unroll
        for (int m = 0; m < 4; m++)
            #pragma unroll
            for (int nt = 0; nt < 2; nt++) {
                const int e = m * 16 + (lane >> 2);
                const int d = dgrp * 16 + nt * 8 + 2 * (lane & 3);
                *(float2*)&outb[e * 64 + d]       = make_float2(kacc[m][nt][0], kacc[m][nt][1]);
                *(float2*)&outb[(e + 8) * 64 + d] = make_float2(kacc[m][nt][2], kacc[m][nt][3]);
            }
        if (lane < 4) {
            #pragma unroll
            for (int nt = 0; nt < 2; nt++) {
                const int d = dgrp * 16 + nt * 8 + 2 * lane;
                *(float2*)&outb[4096 + d] = make_float2(kacc[4][nt][0], kacc[4][nt][1]);
            }
        }
    }
}

// ---------------------------------------------------------------------------
// Weight convert (all three in one launch)
// ---------------------------------------------------------------------------
__global__ void conv_w_all(const float* __restrict__ wqk, const float* __restrict__ wv,
                           const float* __restrict__ wo,
                           __half* __restrict__ oq, __half* __restrict__ ov,
                           __half* __restrict__ oo)
{
    int i = blockIdx.x * 256 + threadIdx.x;
    if (i < 524288) {
        oq[i] = __float2half_rn(wqk[i]);
    } else if (i < 786432) {
        int j = i - 524288; ov[j] = __float2half_rn(wv[j]);
    } else if (i < 1048576) {
        int j = i - 786432; oo[j] = __float2half_rn(wo[j]);
    }
}

// ---------------------------------------------------------------------------
// Transpose + fp16 convert (batches bz0 + blockIdx.z)
// ---------------------------------------------------------------------------
__global__ __launch_bounds__(256) void conv_xt_kernel(
    const float* __restrict__ x, const float* __restrict__ pos,
    __half* __restrict__ xq, __half* __restrict__ xv, int bz0)
{
    __shared__ float sA[64][65];
    __shared__ float sB[64][65];

    const int tid = threadIdx.x;
    const int n0 = blockIdx.x * 64;
    const int c0 = blockIdx.y * 64;
    const int bz = bz0 + blockIdx.z;

    const float* i0 = x   + (size_t)bz * CC * NN;
    const float* i1 = pos + (size_t)bz * CC * NN;

    #pragma unroll
    for (int i = 0; i < 4; i++) {
        int idx = i * 256 + tid;
        int rc = idx >> 4, cn = (idx & 15) * 4;
        float4 xv4 = *(const float4*)&i0[(size_t)(c0 + rc) * NN + n0 + cn];
        float4 pv4 = *(const float4*)&i1[(size_t)(c0 + rc) * NN + n0 + cn];
        sA[rc][cn]     = xv4.x + pv4.x;
        sA[rc][cn + 1] = xv4.y + pv4.y;
        sA[rc][cn + 2] = xv4.z + pv4.z;
        sA[rc][cn + 3] = xv4.w + pv4.w;
        sB[rc][cn]     = xv4.x;
        sB[rc][cn + 1] = xv4.y;
        sB[rc][cn + 2] = xv4.z;
        sB[rc][cn + 3] = xv4.w;
    }
    __syncthreads();

    const size_t obase = ((size_t)bz * NN + n0) * CC + c0;
    #pragma unroll
    for (int i = 0; i < 8; i++) {
        int idx = i * 256 + tid;
        int nr = idx >> 5, cp = idx & 31;
        size_t oa = obase + (size_t)nr * CC + cp * 2;
        __half2 hq, hv;
        hq.x = __float2half_rn(sA[cp * 2][nr]);
        hq.y = __float2half_rn(sA[cp * 2 + 1][nr]);
        hv.x = __float2half_rn(sB[cp * 2][nr]);
        hv.y = __float2half_rn(sB[cp * 2 + 1][nr]);
        *(__half2*)(xq + oa) = hq;
        *(__half2*)(xv + oa) = hv;
    }
}

// ---------------------------------------------------------------------------
// kv reduce for one group of bh (32 bh per group)
// ---------------------------------------------------------------------------
__global__ void kv_reduce(const float* __restrict__ kvp, float* __restrict__ kvout,
                          int bh0)
{
    int i = blockIdx.x * 256 + threadIdx.x;
    if (i < GB * 8 * 4160) {
        size_t j = (size_t)bh0 * 4160 + i;
        float s = 0.f;
        #pragma unroll
        for (int c = 0; c < 32; c++) s += kvp[(size_t)c * (128 * 4160) + j];
        kvout[j] = s;
    }
}

// ---------------------------------------------------------------------------
// attn (tensor cores): out[e,n] = (kv @ q)[e,n] / (ksum@q[n] + EPS)
// ---------------------------------------------------------------------------
#define AT_AH 0
#define AT_AL 10240
#define AT_B  20480
#define AT_SCR 36864
#define ATTN_SMEM 55296

__global__ __launch_bounds__(128) void attn_tc_kernel(
    const __half* __restrict__ qk, const float* __restrict__ kv,
    __half* __restrict__ ao, int bh0)
{
    extern __shared__ __align__(1024) char smem[];
    const uint32_t sbase = smem_u32(smem);
    __half* S1   = (__half*)(smem + AT_SCR);
    __half* sOut = (__half*)(smem + AT_SCR);

    const int tid  = threadIdx.x;
    const int wid  = tid >> 5;
    const int lane = tid & 31;
    const int bh   = bh0 + blockIdx.y;
    const int b = bh >> 3, h = bh & 7;
    const int n0 = blockIdx.x * 128;

    const __half* qbase = qk + ((size_t)b * 2 * CC + h * HD) * NN + n0;
    #pragma unroll
    for (int i = 0; i < 8; i++) {
        int idx = tid + i * 128;
        int d = idx >> 4, j = idx & 15;
        cp_async16(sbase + AT_SCR + (uint32_t)(d * 288 + j * 16),
                   qbase + (size_t)d * NN + j * 8);
    }
    CP_COMMIT();

    {
        uint4 z = {0, 0, 0, 0};
        for (int i = tid; i < 1280; i += 128)
            *(uint4*)(smem + AT_AH + i * 16) = z;
    }
    __syncthreads();
    const float* kvb = kv + (size_t)bh * 4160;
    for (int i = tid; i < 4160; i += 128) {
        int e = i >> 6, d = i & 63;
        float f = kvb[i];
        __half hi = __float2half_rn(f);
        __half lo = __float2half_rn(f - __half2float(hi));
        uint32_t off = SWZ128((uint32_t)(e * 128 + d * 2));
        *(__half*)(smem + AT_AH + off) = hi;
        *(__half*)(smem + AT_AL + off) = lo;
    }
    CP_WAIT(0);
    __syncthreads();

    {
        union { __half hh[8]; uint4 u; } pk;
        const int n = tid;
        #pragma unroll
        for (int j = 0; j < 8; j++) {
            #pragma unroll
            for (int d2 = 0; d2 < 8; d2++)
                pk.hh[d2] = S1[(j * 8 + d2) * 144 + n];
            *(uint4*)(smem + AT_B + SWZ128((uint32_t)(n * 128 + j * 16))) = pk.u;
        }
    }
    __syncthreads();

    float acc[5][4][4];
    #pragma unroll
    for (int m = 0; m < 5; m++)
        #pragma unroll
        for (int nt = 0; nt < 4; nt++)
            #pragma unroll
            for (int e = 0; e < 4; e++) acc[m][nt][e] = 0.f;

    const int a_row  = lane & 15;
    const int a_coff = (lane >> 4) * 16;
    const int b_coff = ((lane >> 3) & 1) * 16;

    #pragma unroll
    for (int ks = 0; ks < 4; ks++) {
        uint32_t ah[5][4], al[5][4], bfr[4][2];
        #pragma unroll
        for (int m = 0; m < 5; m++) {
            const uint32_t so = SWZ128((uint32_t)((m * 16 + a_row) * 128 + ks * 32 + a_coff));
            ldmatrix_x4(ah[m], sbase + AT_AH + so);
            ldmatrix_x4(al[m], sbase + AT_AL + so);
        }
        #pragma unroll
        for (int g = 0; g < 2; g++) {
            const int brow = wid * 32 + g * 16 + ((lane >> 4) << 3) + (lane & 7);
            uint32_t r[4];
            ldmatrix_x4(r, sbase + AT_B + SWZ128((uint32_t)(brow * 128 + ks * 32 + b_coff)));
            bfr[g * 2][0] = r[0];  bfr[g * 2][1] = r[1];
            bfr[g * 2 + 1][0] = r[2];  bfr[g * 2 + 1][1] = r[3];
        }
        #pragma unroll
        for (int m = 0; m < 5; m++)
            #pragma unroll
            for (int nt = 0; nt < 4; nt++) {
                mma_f16(acc[m][nt], ah[m], bfr[nt]);
                mma_f16(acc[m][nt], al[m], bfr[nt]);
            }
    }

    #pragma unroll
    for (int nt = 0; nt < 4; nt++) {
        float den0 = __shfl_sync(0xffffffffu, acc[4][nt][0], lane & 3);
        float den1 = __shfl_sync(0xffffffffu, acc[4][nt][1], lane & 3);
        float inv0 = 1.f / (den0 + EPS);
        float inv1 = 1.f / (den1 + EPS);
        const int n = wid * 32 + nt * 8 + 2 * (lane & 3);
        #pragma unroll
        for (int m = 0; m < 4; m++) {
            const int e = m * 16 + (lane >> 2);
            sOut[n * 72 + e]           = __float2half_rn(acc[m][nt][0] * inv0);
            sOut[(n + 1) * 72 + e]     = __float2half_rn(acc[m][nt][1] * inv1);
            sOut[n * 72 + e + 8]       = __float2half_rn(acc[m][nt][2] * inv0);
            sOut[(n + 1) * 72 + e + 8] = __float2half_rn(acc[m][nt][3] * inv1);
        }
    }
    __syncthreads();

    {
        const int n = tid;
        __half* dst = ao + ((size_t)b * NN + n0 + n) * CC + h * HD;
        #pragma unroll
        for (int j = 0; j < 8; j++)
            *(uint4*)(dst + j * 8) = *(uint4*)(sOut + n * 72 + j * 8);
    }
}

// ---------------------------------------------------------------------------
extern "C" void kernel_launch(void* const* d_in, const int* in_sizes, int n_in,
                              void* d_out, int out_size)
{
    const float* x    = (const float*)d_in[0];
    const float* pos  = (const float*)d_in[1];
    const float* w_qk = (const float*)d_in[2];
    const float* w_v  = (const float*)d_in[3];
    const float* w_o  = (const float*)d_in[4];
    float* out = (float*)d_out;

    __half *qk;
    float *kvp, *kvr;
    cudaGetSymbolAddress((void**)&qk,  g_qkh);
    cudaGetSymbolAddress((void**)&kvp, g_kvp);
    cudaGetSymbolAddress((void**)&kvr, g_kv);
    __half *xq, *xv, *ao, *wq, *wv, *wo;
    cudaGetSymbolAddress((void**)&xq, g_xq);
    cudaGetSymbolAddress((void**)&xv, g_xv);
    cudaGetSymbolAddress((void**)&ao, g_ao);
    cudaGetSymbolAddress((void**)&wq, g_wqk);
    cudaGetSymbolAddress((void**)&wv, g_wv);
    cudaGetSymbolAddress((void**)&wo, g_wo);

    cudaFuncSetAttribute(gemm_tc<true, true>,
                         cudaFuncAttributeMaxDynamicSharedMemorySize, GEMM_SMEM);
    cudaFuncSetAttribute(gemm_tc<false, false>,
                         cudaFuncAttributeMaxDynamicSharedMemorySize, GEMM_SMEM);
    cudaFuncSetAttribute(gemm_v_kv,
                         cudaFuncAttributeMaxDynamicSharedMemorySize, GEMM_SMEM);
    cudaFuncSetAttribute(attn_tc_kernel,
                         cudaFuncAttributeMaxDynamicSharedMemorySize, ATTN_SMEM);

    // R11 orchestration with one fix: forked conv_xt gates on evStart (recorded
    // BEFORE conv_w_all) instead of evRoot, since conv_xt does not read weights.
    // Only each chain's first GEMM gates on evRoot. 3 streams + 5 events, all
    // created once per process (R11-proven safe envelope).
    static cudaStream_t s_st[NGRP - 1];
    static cudaEvent_t  s_evStart, s_evRoot;
    static cudaEvent_t  s_evDone[NGRP - 1];
    static bool s_init = false;
    if (!s_init) {
        for (int g = 0; g < NGRP - 1; g++)
            cudaStreamCreateWithFlags(&s_st[g], cudaStreamNonBlocking);
        cudaEventCreateWithFlags(&s_evStart, cudaEventDisableTiming);
        cudaEventCreateWithFlags(&s_evRoot, cudaEventDisableTiming);
        for (int g = 0; g < NGRP - 1; g++)
            cudaEventCreateWithFlags(&s_evDone[g], cudaEventDisableTiming);
        s_init = true;
    }

    // fork point before any work
    cudaEventRecord(s_evStart, 0);

    // 0) weight converts on origin stream
    conv_w_all<<<4096, 256>>>(w_qk, w_v, w_o, wq, wv, wo);
    cudaEventRecord(s_evRoot, 0);

    auto tail = [&](int g, cudaStream_t stm) {     // everything after conv_xt
        const int bz0 = g * GB;
        const int bh0 = bz0 * NH;
        gemm_tc<true, true><<<dim3(NN / 128, 1024 / 128, GB), 128, GEMM_SMEM, stm>>>(
            wq, xq, qk, 1024, bz0);
        gemm_v_kv<<<dim3(NN / 128, 512 / 128, GB), 128, GEMM_SMEM, stm>>>(
            wv, xv, qk, kvp, bz0);
        kv_reduce<<<(GB * 8 * 4160 + 255) / 256, 256, 0, stm>>>(kvp, kvr, bh0);
        attn_tc_kernel<<<dim3(NN / 128, GB * 8), 128, ATTN_SMEM, stm>>>(
            qk, kvr, ao, bh0);
        gemm_tc<false, false><<<dim3(NN / 128, 512 / 128, GB), 128, GEMM_SMEM, stm>>>(
            wo, ao, out, 512, bz0);
    };

    // group 0 on origin stream (conv_xt ordered after conv_w_all; both tiny
    // relative to the chain, and the origin stream keeps R11's behavior).
    conv_xt_kernel<<<dim3(NN / 64, CC / 64, GB), 256, 0, (cudaStream_t)0>>>(
        x, pos, xq, xv, 0);
    tail(0, (cudaStream_t)0);

    // groups 1..3: conv_xt fires at t=0 (evStart); GEMMs gate on weights.
    for (int g = 1; g < NGRP; g++) {
        cudaStream_t stm = s_st[g - 1];
        cudaStreamWaitEvent(stm, s_evStart, 0);
        conv_xt_kernel<<<dim3(NN / 64, CC / 64, GB), 256, 0, stm>>>(
            x, pos, xq, xv, g * GB);
        cudaStreamWaitEvent(stm, s_evRoot, 0);
        tail(g, stm);
        cudaEventRecord(s_evDone[g - 1], stm);
    }

    // join all branches back to the origin stream
    for (int g = 0; g < NGRP - 1; g++)
        cudaStreamWaitEvent(0, s_evDone[g], 0);
}

// round 16
// speedup vs baseline: 1.0464x; 1.0117x over previous
#include <cuda_runtime.h>
#include <cuda_fp16.h>
#include <cstdint>
#include <cstddef>

// Problem constants
#define BB   16
#define CC   512
#define NN   4096
#define NH   8
#define HD   64
#define EPS  1e-6f
#define NGRP 4
#define GB   (BB / NGRP)   // batches per group = 4

// ---------------------------------------------------------------------------
// Scratch (device globals: allocation-free rule)
// ---------------------------------------------------------------------------
__device__ __half g_qkh[(size_t)BB * 2 * CC * NN]; // [B][1024][4096] relu(qk) fp16
__device__ float g_kvp[(size_t)32 * 128 * 65 * 64];// split-K partials (32 chunks)
__device__ float g_kv [(size_t)128 * 65 * 64];     // [B*nh][65][64] fp32

// fp16 activations, [B][N][C] K-major
__device__ __half g_xq[(size_t)BB * NN * CC];      // x + pos
__device__ __half g_xv[(size_t)BB * NN * CC];      // x
__device__ __half g_ao[(size_t)BB * NN * CC];      // attn output (transposed)
// weights fp16, [O][C] K-major
__device__ __half g_wqk[1024 * 512];
__device__ __half g_wv [512 * 512];
__device__ __half g_wo [512 * 512];

// ---------------------------------------------------------------------------
// Helpers
// ---------------------------------------------------------------------------
__device__ __forceinline__ uint32_t smem_u32(const void* p) {
    uint32_t a;
    asm("{ .reg .u64 t; cvta.to.shared.u64 t, %1; cvt.u32.u64 %0, t; }" : "=r"(a) : "l"(p));
    return a;
}
#define SWZ128(off) ((off) ^ (((off) >> 3) & 0x70))
#define ONES2 0x3C003C00u

__device__ __forceinline__ void cp_async16(uint32_t s, const void* g) {
    asm volatile("cp.async.cg.shared.global [%0], [%1], 16;" :: "r"(s), "l"(g));
}
#define CP_COMMIT() asm volatile("cp.async.commit_group;" ::: "memory")
#define CP_WAIT(n)  asm volatile("cp.async.wait_group %0;" :: "n"(n) : "memory")

__device__ __forceinline__ void ldmatrix_x4(uint32_t* r, uint32_t addr) {
    asm volatile("ldmatrix.sync.aligned.m8n8.x4.shared.b16 {%0,%1,%2,%3}, [%4];"
                 : "=r"(r[0]), "=r"(r[1]), "=r"(r[2]), "=r"(r[3]) : "r"(addr));
}
__device__ __forceinline__ void mma_f16(float* d, const uint32_t* a, const uint32_t* b) {
    asm volatile(
        "mma.sync.aligned.m16n8k16.row.col.f32.f16.f16.f32 "
        "{%0,%1,%2,%3}, {%4,%5,%6,%7}, {%8,%9}, {%0,%1,%2,%3};"
        : "+f"(d[0]), "+f"(d[1]), "+f"(d[2]), "+f"(d[3])
        : "r"(a[0]), "r"(a[1]), "r"(a[2]), "r"(a[3]), "r"(b[0]), "r"(b[1]));
}

// 128-thread GEMM config: BM=128, BN=128, BK=64, warp tile 64x64, 3 stages.
#define BKB 128
#define B_OFF  16384
#define STG    32768
#define GEMM_SMEM (3 * STG)

// ---------------------------------------------------------------------------
// qk / o projection GEMM:  Y[O,N] = W[O,C] @ X[C,N]  (batches bz0 + blockIdx.z)
// R11 mainloop (compute, then prefetch it+2, then WAIT(1) on stage it+1 which
// has had a full compute block to land). Ring counters replace % 3.
// ---------------------------------------------------------------------------
template<bool RELU, bool HOUT>
__global__ __launch_bounds__(128, 2) void gemm_tc(
    const __half* __restrict__ A, const __half* __restrict__ Bx,
    void* __restrict__ Yv, int O, int bz0)
{
    extern __shared__ __align__(1024) char smem[];
    const uint32_t sbase = smem_u32(smem);
    const int tid  = threadIdx.x;
    const int wid  = tid >> 5;
    const int lane = tid & 31;
    const int wm   = wid & 1;
    const int wn   = wid >> 1;

    const int n0 = blockIdx.x * 128;
    const int o0 = blockIdx.y * 128;
    const int bz = bz0 + blockIdx.z;

    const __half* Bb = Bx + (size_t)bz * NN * CC;

    auto load_stage = [&](int ck, int st) {
        const int k0 = ck * 64;
        const uint32_t sb = sbase + st * STG;
        #pragma unroll
        for (int i = 0; i < 8; i++) {
            int c = tid + i * 128;
            int row = c >> 3, cc = c & 7;
            cp_async16(sb + SWZ128((uint32_t)(row * BKB + cc * 16)),
                       A + (size_t)(o0 + row) * CC + k0 + cc * 8);
        }
        #pragma unroll
        for (int i = 0; i < 8; i++) {
            int c = tid + i * 128;
            int row = c >> 3, cc = c & 7;
            cp_async16(sb + B_OFF + SWZ128((uint32_t)(row * BKB + cc * 16)),
                       Bb + (size_t)(n0 + row) * CC + k0 + cc * 8);
        }
        CP_COMMIT();
    };

    float acc[4][8][4];
    #pragma unroll
    for (int mf = 0; mf < 4; mf++)
        #pragma unroll
        for (int nf = 0; nf < 8; nf++)
            #pragma unroll
            for (int e = 0; e < 4; e++) acc[mf][nf][e] = 0.f;

    load_stage(0, 0);
    load_stage(1, 1);
    CP_WAIT(1);
    __syncthreads();

    const int a_row  = wm * 64 + (lane & 15);
    const int a_coff = (lane >> 4) * 16;
    const int b_row  = wn * 64 + ((lane >> 4) << 3) + (lane & 7);
    const int b_coff = ((lane >> 3) & 1) * 16;

    int stc = 0;                      // compute stage ring
    int stp = 2;                      // prefetch stage ring (stage of it+2)
    for (int it = 0; it < 8; it++) {
        const uint32_t sb = sbase + stc * STG;
        #pragma unroll
        for (int kk = 0; kk < 4; kk++) {
            uint32_t a[4][4], b[8][2];
            #pragma unroll
            for (int mf = 0; mf < 4; mf++)
                ldmatrix_x4(a[mf], sb +
                            SWZ128((uint32_t)((a_row + mf * 16) * BKB + kk * 32 + a_coff)));
            #pragma unroll
            for (int ng = 0; ng < 4; ng++) {
                uint32_t r[4];
                ldmatrix_x4(r, sb + B_OFF +
                            SWZ128((uint32_t)((b_row + ng * 16) * BKB + kk * 32 + b_coff)));
                b[ng * 2][0] = r[0];  b[ng * 2][1] = r[1];
                b[ng * 2 + 1][0] = r[2];  b[ng * 2 + 1][1] = r[3];
            }
            #pragma unroll
            for (int mf = 0; mf < 4; mf++)
                #pragma unroll
                for (int nf = 0; nf < 8; nf++)
                    mma_f16(acc[mf][nf], a[mf], b[nf]);
        }
        if (it + 2 < 8) {
            load_stage(it + 2, stp);
            CP_WAIT(1);
        } else {
            CP_WAIT(0);
        }
        __syncthreads();
        stc = (stc == 2) ? 0 : stc + 1;
        stp = (stp == 2) ? 0 : stp + 1;
    }

    const int er = lane >> 2;
    const int ec = (lane & 3) * 2;
    #pragma unroll
    for (int mf = 0; mf < 4; mf++) {
        #pragma unroll
        for (int nf = 0; nf < 8; nf++) {
            const int orow = o0 + wm * 64 + mf * 16 + er;
            const int ocol = n0 + wn * 64 + nf * 8 + ec;
            float v0x = acc[mf][nf][0], v0y = acc[mf][nf][1];
            float v1x = acc[mf][nf][2], v1y = acc[mf][nf][3];
            if (RELU) {
                v0x = fmaxf(v0x, 0.f); v0y = fmaxf(v0y, 0.f);
                v1x = fmaxf(v1x, 0.f); v1y = fmaxf(v1y, 0.f);
            }
            if (HOUT) {
                __half* Yb = (__half*)Yv + (size_t)bz * O * NN;
                *(__half2*)&Yb[(size_t)orow * NN + ocol] = __floats2half2_rn(v0x, v0y);
                *(__half2*)&Yb[(size_t)(orow + 8) * NN + ocol] = __floats2half2_rn(v1x, v1y);
            } else {
                float* Yb = (float*)Yv + (size_t)bz * O * NN;
                *(float2*)&Yb[(size_t)orow * NN + ocol]       = make_float2(v0x, v0y);
                *(float2*)&Yb[(size_t)(orow + 8) * NN + ocol] = make_float2(v1x, v1y);
            }
        }
    }
}

// ---------------------------------------------------------------------------
// Fused v-GEMM + kv (batches bz0 + blockIdx.z)
// ---------------------------------------------------------------------------
#define VP 136
#define KV_KOFF 34816

__global__ __launch_bounds__(128, 2) void gemm_v_kv(
    const __half* __restrict__ A, const __half* __restrict__ Bx,
    const __half* __restrict__ qk, float* __restrict__ kvp, int bz0)
{
    extern __shared__ __align__(1024) char smem[];
    const uint32_t sbase = smem_u32(smem);
    const int tid  = threadIdx.x;
    const int wid  = tid >> 5;
    const int lane = tid & 31;
    const int wm   = wid & 1;
    const int wn   = wid >> 1;

    const int n0 = blockIdx.x * 128;
    const int o0 = blockIdx.y * 128;
    const int bz = bz0 + blockIdx.z;

    const __half* Bb = Bx + (size_t)bz * NN * CC;

    auto load_stage = [&](int ck, int st) {
        const int k0 = ck * 64;
        const uint32_t sb = sbase + st * STG;
        #pragma unroll
        for (int i = 0; i < 8; i++) {
            int c = tid + i * 128;
            int row = c >> 3, cc = c & 7;
            cp_async16(sb + SWZ128((uint32_t)(row * BKB + cc * 16)),
                       A + (size_t)(o0 + row) * CC + k0 + cc * 8);
        }
        #pragma unroll
        for (int i = 0; i < 8; i++) {
            int c = tid + i * 128;
            int row = c >> 3, cc = c & 7;
            cp_async16(sb + B_OFF + SWZ128((uint32_t)(row * BKB + cc * 16)),
                       Bb + (size_t)(n0 + row) * CC + k0 + cc * 8);
        }
        CP_COMMIT();
    };

    float acc[4][8][4];
    #pragma unroll
    for (int mf = 0; mf < 4; mf++)
        #pragma unroll
        for (int nf = 0; nf < 8; nf++)
            #pragma unroll
            for (int e = 0; e < 4; e++) acc[mf][nf][e] = 0.f;

    load_stage(0, 0);
    load_stage(1, 1);
    CP_WAIT(1);
    __syncthreads();

    const int a_row  = wm * 64 + (lane & 15);
    const int a_coff = (lane >> 4) * 16;
    const int b_row  = wn * 64 + ((lane >> 4) << 3) + (lane & 7);
    const int b_coff = ((lane >> 3) & 1) * 16;

    int stc = 0;
    int stp = 2;
    for (int it = 0; it < 8; it++) {
        const uint32_t sb = sbase + stc * STG;
        #pragma unroll
        for (int kk = 0; kk < 4; kk++) {
            uint32_t a[4][4], b[8][2];
            #pragma unroll
            for (int mf = 0; mf < 4; mf++)
                ldmatrix_x4(a[mf], sb +
                            SWZ128((uint32_t)((a_row + mf * 16) * BKB + kk * 32 + a_coff)));
            #pragma unroll
            for (int ng = 0; ng < 4; ng++) {
                uint32_t r[4];
                ldmatrix_x4(r, sb + B_OFF +
                            SWZ128((uint32_t)((b_row + ng * 16) * BKB + kk * 32 + b_coff)));
                b[ng * 2][0] = r[0];  b[ng * 2][1] = r[1];
                b[ng * 2 + 1][0] = r[2];  b[ng * 2 + 1][1] = r[3];
            }
            #pragma unroll
            for (int mf = 0; mf < 4; mf++)
                #pragma unroll
                for (int nf = 0; nf < 8; nf++)
                    mma_f16(acc[mf][nf], a[mf], b[nf]);
        }
        if (it + 2 < 8) {
            load_stage(it + 2, stp);
            CP_WAIT(1);
        } else {
            CP_WAIT(0);
        }
        __syncthreads();
        stc = (stc == 2) ? 0 : stc + 1;
        stp = (stp == 2) ? 0 : stp + 1;
    }

    // ---- epilogue: v tile (fp16) -> smem [128][VP]; k tile -> smem ----
    __half* sv = (__half*)smem;
    const int er = lane >> 2;
    const int ec = (lane & 3) * 2;
    #pragma unroll
    for (int mf = 0; mf < 4; mf++) {
        #pragma unroll
        for (int nf = 0; nf < 8; nf++) {
            const int lr = wm * 64 + mf * 16 + er;
            const int lc = wn * 64 + nf * 8 + ec;
            *(__half2*)&sv[lr * VP + lc] =
                __floats2half2_rn(acc[mf][nf][0], acc[mf][nf][1]);
            *(__half2*)&sv[(lr + 8) * VP + lc] =
                __floats2half2_rn(acc[mf][nf][2], acc[mf][nf][3]);
        }
    }
    const __half* kb = qk + ((size_t)bz * 2 * CC + CC + o0) * NN + n0;
    #pragma unroll
    for (int i = 0; i < 16; i++) {
        int idx = tid + i * 128;
        int r = idx >> 4, c = idx & 15;
        cp_async16(sbase + KV_KOFF + (uint32_t)(r * 272 + c * 16),
                   kb + (size_t)r * NN + c * 8);
    }
    CP_COMMIT();
    CP_WAIT(0);
    __syncthreads();

    const int dgrp = wid;
    const int arow2 = lane & 15;
    const int acoff2 = (lane >> 4) * 16;
    const int bcoff2 = ((lane >> 3) & 1) * 16;
    const uint32_t ones[4] = {ONES2, ONES2, ONES2, ONES2};

    for (int head = 0; head < 2; head++) {
        float kacc[5][2][4];
        #pragma unroll
        for (int m = 0; m < 5; m++)
            #pragma unroll
            for (int nt = 0; nt < 2; nt++)
                #pragma unroll
                for (int e = 0; e < 4; e++) kacc[m][nt][e] = 0.f;

        const int brow2 = head * 64 + dgrp * 16 + ((lane >> 4) << 3) + (lane & 7);
        #pragma unroll
        for (int ks = 0; ks < 8; ks++) {
            uint32_t bf[4];
            ldmatrix_x4(bf, sbase + KV_KOFF + (uint32_t)(brow2 * 272 + ks * 32 + bcoff2));
            uint32_t b0[2] = {bf[0], bf[1]}, b1[2] = {bf[2], bf[3]};
            #pragma unroll
            for (int m = 0; m < 4; m++) {
                uint32_t a[4];
                ldmatrix_x4(a, sbase +
                            (uint32_t)((head * 64 + m * 16 + arow2) * 272 + ks * 32 + acoff2));
                mma_f16(kacc[m][0], a, b0);
                mma_f16(kacc[m][1], a, b1);
            }
            mma_f16(kacc[4][0], ones, b0);
            mma_f16(kacc[4][1], ones, b1);
        }

        const int bh = bz * 8 + blockIdx.y * 2 + head;
        float* outb = kvp + (size_t)blockIdx.x * (128 * 4160) + (size_t)bh * 4160;
        #pragma unroll
        for (int m = 0; m < 4; m++)
            #pragma unroll
            for (int nt = 0; nt < 2; nt++) {
                const int e = m * 16 + (lane >> 2);
                const int d = dgrp * 16 + nt * 8 + 2 * (lane & 3);
                *(float2*)&outb[e * 64 + d]       = make_float2(kacc[m][nt][0], kacc[m][nt][1]);
                *(float2*)&outb[(e + 8) * 64 + d] = make_float2(kacc[m][nt][2], kacc[m][nt][3]);
            }
        if (lane < 4) {
            #pragma unroll
            for (int nt = 0; nt < 2; nt++) {
                const int d = dgrp * 16 + nt * 8 + 2 * lane;
                *(float2*)&outb[4096 + d] = make_float2(kacc[4][nt][0], kacc[4][nt][1]);
            }
        }
    }
}

// ---------------------------------------------------------------------------
// Weight convert (all three in one launch)
// ---------------------------------------------------------------------------
__global__ void conv_w_all(const float* __restrict__ wqk, const float* __restrict__ wv,
                           const float* __restrict__ wo,
                           __half* __restrict__ oq, __half* __restrict__ ov,
                           __half* __restrict__ oo)
{
    int i = blockIdx.x * 256 + threadIdx.x;
    if (i < 524288) {
        oq[i] = __float2half_rn(wqk[i]);
    } else if (i < 786432) {
        int j = i - 524288; ov[j] = __float2half_rn(wv[j]);
    } else if (i < 1048576) {
        int j = i - 786432; oo[j] = __float2half_rn(wo[j]);
    }
}

// ---------------------------------------------------------------------------
// Transpose + fp16 convert (batches bz0 + blockIdx.z)
// ---------------------------------------------------------------------------
__global__ __launch_bounds__(256) void conv_xt_kernel(
    const float* __restrict__ x, const float* __restrict__ pos,
    __half* __restrict__ xq, __half* __restrict__ xv, int bz0)
{
    __shared__ float sA[64][65];
    __shared__ float sB[64][65];

    const int tid = threadIdx.x;
    const int n0 = blockIdx.x * 64;
    const int c0 = blockIdx.y * 64;
    const int bz = bz0 + blockIdx.z;

    const float* i0 = x   + (size_t)bz * CC * NN;
    const float* i1 = pos + (size_t)bz * CC * NN;

    #pragma unroll
    for (int i = 0; i < 4; i++) {
        int idx = i * 256 + tid;
        int rc = idx >> 4, cn = (idx & 15) * 4;
        float4 xv4 = *(const float4*)&i0[(size_t)(c0 + rc) * NN + n0 + cn];
        float4 pv4 = *(const float4*)&i1[(size_t)(c0 + rc) * NN + n0 + cn];
        sA[rc][cn]     = xv4.x + pv4.x;
        sA[rc][cn + 1] = xv4.y + pv4.y;
        sA[rc][cn + 2] = xv4.z + pv4.z;
        sA[rc][cn + 3] = xv4.w + pv4.w;
        sB[rc][cn]     = xv4.x;
        sB[rc][cn + 1] = xv4.y;
        sB[rc][cn + 2] = xv4.z;
        sB[rc][cn + 3] = xv4.w;
    }
    __syncthreads();

    const size_t obase = ((size_t)bz * NN + n0) * CC + c0;
    #pragma unroll
    for (int i = 0; i < 8; i++) {
        int idx = i * 256 + tid;
        int nr = idx >> 5, cp = idx & 31;
        size_t oa = obase + (size_t)nr * CC + cp * 2;
        __half2 hq, hv;
        hq.x = __float2half_rn(sA[cp * 2][nr]);
        hq.y = __float2half_rn(sA[cp * 2 + 1][nr]);
        hv.x = __float2half_rn(sB[cp * 2][nr]);
        hv.y = __float2half_rn(sB[cp * 2 + 1][nr]);
        *(__half2*)(xq + oa) = hq;
        *(__half2*)(xv + oa) = hv;
    }
}

// ---------------------------------------------------------------------------
// kv reduce for one group of bh (32 bh per group)
// ---------------------------------------------------------------------------
__global__ void kv_reduce(const float* __restrict__ kvp, float* __restrict__ kvout,
                          int bh0)
{
    int i = blockIdx.x * 256 + threadIdx.x;
    if (i < GB * 8 * 4160) {
        size_t j = (size_t)bh0 * 4160 + i;
        float s = 0.f;
        #pragma unroll
        for (int c = 0; c < 32; c++) s += kvp[(size_t)c * (128 * 4160) + j];
        kvout[j] = s;
    }
}

// ---------------------------------------------------------------------------
// attn (tensor cores): out[e,n] = (kv @ q)[e,n] / (ksum@q[n] + EPS)
// ---------------------------------------------------------------------------
#define AT_AH 0
#define AT_AL 10240
#define AT_B  20480
#define AT_SCR 36864
#define ATTN_SMEM 55296

__global__ __launch_bounds__(128) void attn_tc_kernel(
    const __half* __restrict__ qk, const float* __restrict__ kv,
    __half* __restrict__ ao, int bh0)
{
    extern __shared__ __align__(1024) char smem[];
    const uint32_t sbase = smem_u32(smem);
    __half* S1   = (__half*)(smem + AT_SCR);
    __half* sOut = (__half*)(smem + AT_SCR);

    const int tid  = threadIdx.x;
    const int wid  = tid >> 5;
    const int lane = tid & 31;
    const int bh   = bh0 + blockIdx.y;
    const int b = bh >> 3, h = bh & 7;
    const int n0 = blockIdx.x * 128;

    const __half* qbase = qk + ((size_t)b * 2 * CC + h * HD) * NN + n0;
    #pragma unroll
    for (int i = 0; i < 8; i++) {
        int idx = tid + i * 128;
        int d = idx >> 4, j = idx & 15;
        cp_async16(sbase + AT_SCR + (uint32_t)(d * 288 + j * 16),
                   qbase + (size_t)d * NN + j * 8);
    }
    CP_COMMIT();

    {
        uint4 z = {0, 0, 0, 0};
        for (int i = tid; i < 1280; i += 128)
            *(uint4*)(smem + AT_AH + i * 16) = z;
    }
    __syncthreads();
    const float* kvb = kv + (size_t)bh * 4160;
    for (int i = tid; i < 4160; i += 128) {
        int e = i >> 6, d = i & 63;
        float f = kvb[i];
        __half hi = __float2half_rn(f);
        __half lo = __float2half_rn(f - __half2float(hi));
        uint32_t off = SWZ128((uint32_t)(e * 128 + d * 2));
        *(__half*)(smem + AT_AH + off) = hi;
        *(__half*)(smem + AT_AL + off) = lo;
    }
    CP_WAIT(0);
    __syncthreads();

    {
        union { __half hh[8]; uint4 u; } pk;
        const int n = tid;
        #pragma unroll
        for (int j = 0; j < 8; j++) {
            #pragma unroll
            for (int d2 = 0; d2 < 8; d2++)
                pk.hh[d2] = S1[(j * 8 + d2) * 144 + n];
            *(uint4*)(smem + AT_B + SWZ128((uint32_t)(n * 128 + j * 16))) = pk.u;
        }
    }
    __syncthreads();

    float acc[5][4][4];
    #pragma unroll
    for (int m = 0; m < 5; m++)
        #pragma unroll
        for (int nt = 0; nt < 4; nt++)
            #pragma unroll
            for (int e = 0; e < 4; e++) acc[m][nt][e] = 0.f;

    const int a_row  = lane & 15;
    const int a_coff = (lane >> 4) * 16;
    const int b_coff = ((lane >> 3) & 1) * 16;

    #pragma unroll
    for (int ks = 0; ks < 4; ks++) {
        uint32_t ah[5][4], al[5][4], bfr[4][2];
        #pragma unroll
        for (int m = 0; m < 5; m++) {
            const uint32_t so = SWZ128((uint32_t)((m * 16 + a_row) * 128 + ks * 32 + a_coff));
            ldmatrix_x4(ah[m], sbase + AT_AH + so);
            ldmatrix_x4(al[m], sbase + AT_AL + so);
        }
        #pragma unroll
        for (int g = 0; g < 2; g++) {
            const int brow = wid * 32 + g * 16 + ((lane >> 4) << 3) + (lane & 7);
            uint32_t r[4];
            ldmatrix_x4(r, sbase + AT_B + SWZ128((uint32_t)(brow * 128 + ks * 32 + b_coff)));
            bfr[g * 2][0] = r[0];  bfr[g * 2][1] = r[1];
            bfr[g * 2 + 1][0] = r[2];  bfr[g * 2 + 1][1] = r[3];
        }
        #pragma unroll
        for (int m = 0; m < 5; m++)
            #pragma unroll
            for (int nt = 0; nt < 4; nt++) {
                mma_f16(acc[m][nt], ah[m], bfr[nt]);
                mma_f16(acc[m][nt], al[m], bfr[nt]);
            }
    }

    #pragma unroll
    for (int nt = 0; nt < 4; nt++) {
        float den0 = __shfl_sync(0xffffffffu, acc[4][nt][0], lane & 3);
        float den1 = __shfl_sync(0xffffffffu, acc[4][nt][1], lane & 3);
        float inv0 = 1.f / (den0 + EPS);
        float inv1 = 1.f / (den1 + EPS);
        const int n = wid * 32 + nt * 8 + 2 * (lane & 3);
        #pragma unroll
        for (int m = 0; m < 4; m++) {
            const int e = m * 16 + (lane >> 2);
            sOut[n * 72 + e]           = __float2half_rn(acc[m][nt][0] * inv0);
            sOut[(n + 1) * 72 + e]     = __float2half_rn(acc[m][nt][1] * inv1);
            sOut[n * 72 + e + 8]       = __float2half_rn(acc[m][nt][2] * inv0);
            sOut[(n + 1) * 72 + e + 8] = __float2half_rn(acc[m][nt][3] * inv1);
        }
    }
    __syncthreads();

    {
        const int n = tid;
        __half* dst = ao + ((size_t)b * NN + n0 + n) * CC + h * HD;
        #pragma unroll
        for (int j = 0; j < 8; j++)
            *(uint4*)(dst + j * 8) = *(uint4*)(sOut + n * 72 + j * 8);
    }
}

// ---------------------------------------------------------------------------
extern "C" void kernel_launch(void* const* d_in, const int* in_sizes, int n_in,
                              void* d_out, int out_size)
{
    const float* x    = (const float*)d_in[0];
    const float* pos  = (const float*)d_in[1];
    const float* w_qk = (const float*)d_in[2];
    const float* w_v  = (const float*)d_in[3];
    const float* w_o  = (const float*)d_in[4];
    float* out = (float*)d_out;

    __half *qk;
    float *kvp, *kvr;
    cudaGetSymbolAddress((void**)&qk,  g_qkh);
    cudaGetSymbolAddress((void**)&kvp, g_kvp);
    cudaGetSymbolAddress((void**)&kvr, g_kv);
    __half *xq, *xv, *ao, *wq, *wv, *wo;
    cudaGetSymbolAddress((void**)&xq, g_xq);
    cudaGetSymbolAddress((void**)&xv, g_xv);
    cudaGetSymbolAddress((void**)&ao, g_ao);
    cudaGetSymbolAddress((void**)&wq, g_wqk);
    cudaGetSymbolAddress((void**)&wv, g_wv);
    cudaGetSymbolAddress((void**)&wo, g_wo);

    cudaFuncSetAttribute(gemm_tc<true, true>,
                         cudaFuncAttributeMaxDynamicSharedMemorySize, GEMM_SMEM);
    cudaFuncSetAttribute(gemm_tc<false, false>,
                         cudaFuncAttributeMaxDynamicSharedMemorySize, GEMM_SMEM);
    cudaFuncSetAttribute(gemm_v_kv,
                         cudaFuncAttributeMaxDynamicSharedMemorySize, GEMM_SMEM);
    cudaFuncSetAttribute(attn_tc_kernel,
                         cudaFuncAttributeMaxDynamicSharedMemorySize, ATTN_SMEM);

    // R11 orchestration exactly (champion config; all checkpoints clean):
    // 3 forked streams + origin, phase-concurrent groups, handles created once.
    static cudaStream_t s_st[NGRP - 1];
    static cudaEvent_t  s_evRoot;
    static cudaEvent_t  s_evDone[NGRP - 1];
    static bool s_init = false;
    if (!s_init) {
        for (int g = 0; g < NGRP - 1; g++)
            cudaStreamCreateWithFlags(&s_st[g], cudaStreamNonBlocking);
        cudaEventCreateWithFlags(&s_evRoot, cudaEventDisableTiming);
        for (int g = 0; g < NGRP - 1; g++)
            cudaEventCreateWithFlags(&s_evDone[g], cudaEventDisableTiming);
        s_init = true;
    }

    // 0) weight converts on origin stream
    conv_w_all<<<4096, 256>>>(w_qk, w_v, w_o, wq, wv, wo);
    cudaEventRecord(s_evRoot, 0);

    auto chain = [&](int g, cudaStream_t stm) {
        const int bz0 = g * GB;
        const int bh0 = bz0 * NH;

        conv_xt_kernel<<<dim3(NN / 64, CC / 64, GB), 256, 0, stm>>>(
            x, pos, xq, xv, bz0);
        gemm_tc<true, true><<<dim3(NN / 128, 1024 / 128, GB), 128, GEMM_SMEM, stm>>>(
            wq, xq, qk, 1024, bz0);
        gemm_v_kv<<<dim3(NN / 128, 512 / 128, GB), 128, GEMM_SMEM, stm>>>(
            wv, xv, qk, kvp, bz0);
        kv_reduce<<<(GB * 8 * 4160 + 255) / 256, 256, 0, stm>>>(kvp, kvr, bh0);
        attn_tc_kernel<<<dim3(NN / 128, GB * 8), 128, ATTN_SMEM, stm>>>(
            qk, kvr, ao, bh0);
        gemm_tc<false, false><<<dim3(NN / 128, 512 / 128, GB), 128, GEMM_SMEM, stm>>>(
            wo, ao, out, 512, bz0);
    };

    // group 0 on the origin stream (ordered after conv_w_all implicitly)
    chain(0, (cudaStream_t)0);

    // groups 1..3 on forked streams
    for (int g = 1; g < NGRP; g++) {
        cudaStreamWaitEvent(s_st[g - 1], s_evRoot, 0);
        chain(g, s_st[g - 1]);
        cudaEventRecord(s_evDone[g - 1], s_st[g - 1]);
    }

    // join all branches back to the origin stream
    for (int g = 0; g < NGRP - 1; g++)
        cudaStreamWaitEvent(0, s_evDone[g], 0);
}

// round 17
// speedup vs baseline: 1.0501x; 1.0035x over previous
#include <cuda_runtime.h>
#include <cuda_fp16.h>
#include <cstdint>
#include <cstddef>

// Problem constants
#define BB   16
#define CC   512
#define NN   4096
#define NH   8
#define HD   64
#define EPS  1e-6f
#define NGRP 8
#define GB   (BB / NGRP)   // batches per group = 2
#define NSTR 4             // stream lanes (origin + 3 forked)

// ---------------------------------------------------------------------------
// Scratch (device globals: allocation-free rule)
// ---------------------------------------------------------------------------
__device__ __half g_qkh[(size_t)BB * 2 * CC * NN]; // [B][1024][4096] relu(qk) fp16
__device__ float g_kvp[(size_t)32 * 128 * 65 * 64];// split-K partials (32 chunks)
__device__ float g_kv [(size_t)128 * 65 * 64];     // [B*nh][65][64] fp32

// fp16 activations, [B][N][C] K-major
__device__ __half g_xq[(size_t)BB * NN * CC];      // x + pos
__device__ __half g_xv[(size_t)BB * NN * CC];      // x
__device__ __half g_ao[(size_t)BB * NN * CC];      // attn output (transposed)
// weights fp16, [O][C] K-major
__device__ __half g_wqk[1024 * 512];
__device__ __half g_wv [512 * 512];
__device__ __half g_wo [512 * 512];

// ---------------------------------------------------------------------------
// Helpers
// ---------------------------------------------------------------------------
__device__ __forceinline__ uint32_t smem_u32(const void* p) {
    uint32_t a;
    asm("{ .reg .u64 t; cvta.to.shared.u64 t, %1; cvt.u32.u64 %0, t; }" : "=r"(a) : "l"(p));
    return a;
}
#define SWZ128(off) ((off) ^ (((off) >> 3) & 0x70))
#define ONES2 0x3C003C00u

__device__ __forceinline__ void cp_async16(uint32_t s, const void* g) {
    asm volatile("cp.async.cg.shared.global [%0], [%1], 16;" :: "r"(s), "l"(g));
}
#define CP_COMMIT() asm volatile("cp.async.commit_group;" ::: "memory")
#define CP_WAIT(n)  asm volatile("cp.async.wait_group %0;" :: "n"(n) : "memory")

__device__ __forceinline__ void ldmatrix_x4(uint32_t* r, uint32_t addr) {
    asm volatile("ldmatrix.sync.aligned.m8n8.x4.shared.b16 {%0,%1,%2,%3}, [%4];"
                 : "=r"(r[0]), "=r"(r[1]), "=r"(r[2]), "=r"(r[3]) : "r"(addr));
}
__device__ __forceinline__ void mma_f16(float* d, const uint32_t* a, const uint32_t* b) {
    asm volatile(
        "mma.sync.aligned.m16n8k16.row.col.f32.f16.f16.f32 "
        "{%0,%1,%2,%3}, {%4,%5,%6,%7}, {%8,%9}, {%0,%1,%2,%3};"
        : "+f"(d[0]), "+f"(d[1]), "+f"(d[2]), "+f"(d[3])
        : "r"(a[0]), "r"(a[1]), "r"(a[2]), "r"(a[3]), "r"(b[0]), "r"(b[1]));
}

// 128-thread GEMM config: BM=128, BN=128, BK=64, warp tile 64x64, 3 stages.
#define BKB 128
#define B_OFF  16384
#define STG    32768
#define GEMM_SMEM (3 * STG)

// ---------------------------------------------------------------------------
// qk / o projection GEMM:  Y[O,N] = W[O,C] @ X[C,N]  (batches bz0 + blockIdx.z)
// ---------------------------------------------------------------------------
template<bool RELU, bool HOUT>
__global__ __launch_bounds__(128, 2) void gemm_tc(
    const __half* __restrict__ A, const __half* __restrict__ Bx,
    void* __restrict__ Yv, int O, int bz0)
{
    extern __shared__ __align__(1024) char smem[];
    const uint32_t sbase = smem_u32(smem);
    const int tid  = threadIdx.x;
    const int wid  = tid >> 5;
    const int lane = tid & 31;
    const int wm   = wid & 1;
    const int wn   = wid >> 1;

    const int n0 = blockIdx.x * 128;
    const int o0 = blockIdx.y * 128;
    const int bz = bz0 + blockIdx.z;

    const __half* Bb = Bx + (size_t)bz * NN * CC;

    auto load_stage = [&](int ck, int st) {
        const int k0 = ck * 64;
        const uint32_t sb = sbase + st * STG;
        #pragma unroll
        for (int i = 0; i < 8; i++) {
            int c = tid + i * 128;
            int row = c >> 3, cc = c & 7;
            cp_async16(sb + SWZ128((uint32_t)(row * BKB + cc * 16)),
                       A + (size_t)(o0 + row) * CC + k0 + cc * 8);
        }
        #pragma unroll
        for (int i = 0; i < 8; i++) {
            int c = tid + i * 128;
            int row = c >> 3, cc = c & 7;
            cp_async16(sb + B_OFF + SWZ128((uint32_t)(row * BKB + cc * 16)),
                       Bb + (size_t)(n0 + row) * CC + k0 + cc * 8);
        }
        CP_COMMIT();
    };

    float acc[4][8][4];
    #pragma unroll
    for (int mf = 0; mf < 4; mf++)
        #pragma unroll
        for (int nf = 0; nf < 8; nf++)
            #pragma unroll
            for (int e = 0; e < 4; e++) acc[mf][nf][e] = 0.f;

    load_stage(0, 0);
    load_stage(1, 1);
    CP_WAIT(1);
    __syncthreads();

    const int a_row  = wm * 64 + (lane & 15);
    const int a_coff = (lane >> 4) * 16;
    const int b_row  = wn * 64 + ((lane >> 4) << 3) + (lane & 7);
    const int b_coff = ((lane >> 3) & 1) * 16;

    int stc = 0;                      // compute stage ring
    int stp = 2;                      // prefetch stage ring (stage of it+2)
    for (int it = 0; it < 8; it++) {
        const uint32_t sb = sbase + stc * STG;
        #pragma unroll
        for (int kk = 0; kk < 4; kk++) {
            uint32_t a[4][4], b[8][2];
            #pragma unroll
            for (int mf = 0; mf < 4; mf++)
                ldmatrix_x4(a[mf], sb +
                            SWZ128((uint32_t)((a_row + mf * 16) * BKB + kk * 32 + a_coff)));
            #pragma unroll
            for (int ng = 0; ng < 4; ng++) {
                uint32_t r[4];
                ldmatrix_x4(r, sb + B_OFF +
                            SWZ128((uint32_t)((b_row + ng * 16) * BKB + kk * 32 + b_coff)));
                b[ng * 2][0] = r[0];  b[ng * 2][1] = r[1];
                b[ng * 2 + 1][0] = r[2];  b[ng * 2 + 1][1] = r[3];
            }
            #pragma unroll
            for (int mf = 0; mf < 4; mf++)
                #pragma unroll
                for (int nf = 0; nf < 8; nf++)
                    mma_f16(acc[mf][nf], a[mf], b[nf]);
        }
        if (it + 2 < 8) {
            load_stage(it + 2, stp);
            CP_WAIT(1);
        } else {
            CP_WAIT(0);
        }
        __syncthreads();
        stc = (stc == 2) ? 0 : stc + 1;
        stp = (stp == 2) ? 0 : stp + 1;
    }

    const int er = lane >> 2;
    const int ec = (lane & 3) * 2;
    #pragma unroll
    for (int mf = 0; mf < 4; mf++) {
        #pragma unroll
        for (int nf = 0; nf < 8; nf++) {
            const int orow = o0 + wm * 64 + mf * 16 + er;
            const int ocol = n0 + wn * 64 + nf * 8 + ec;
            float v0x = acc[mf][nf][0], v0y = acc[mf][nf][1];
            float v1x = acc[mf][nf][2], v1y = acc[mf][nf][3];
            if (RELU) {
                v0x = fmaxf(v0x, 0.f); v0y = fmaxf(v0y, 0.f);
                v1x = fmaxf(v1x, 0.f); v1y = fmaxf(v1y, 0.f);
            }
            if (HOUT) {
                __half* Yb = (__half*)Yv + (size_t)bz * O * NN;
                *(__half2*)&Yb[(size_t)orow * NN + ocol] = __floats2half2_rn(v0x, v0y);
                *(__half2*)&Yb[(size_t)(orow + 8) * NN + ocol] = __floats2half2_rn(v1x, v1y);
            } else {
                float* Yb = (float*)Yv + (size_t)bz * O * NN;
                *(float2*)&Yb[(size_t)orow * NN + ocol]       = make_float2(v0x, v0y);
                *(float2*)&Yb[(size_t)(orow + 8) * NN + ocol] = make_float2(v1x, v1y);
            }
        }
    }
}

// ---------------------------------------------------------------------------
// Fused v-GEMM + kv (batches bz0 + blockIdx.z)
// ---------------------------------------------------------------------------
#define VP 136
#define KV_KOFF 34816

__global__ __launch_bounds__(128, 2) void gemm_v_kv(
    const __half* __restrict__ A, const __half* __restrict__ Bx,
    const __half* __restrict__ qk, float* __restrict__ kvp, int bz0)
{
    extern __shared__ __align__(1024) char smem[];
    const uint32_t sbase = smem_u32(smem);
    const int tid  = threadIdx.x;
    const int wid  = tid >> 5;
    const int lane = tid & 31;
    const int wm   = wid & 1;
    const int wn   = wid >> 1;

    const int n0 = blockIdx.x * 128;
    const int o0 = blockIdx.y * 128;
    const int bz = bz0 + blockIdx.z;

    const __half* Bb = Bx + (size_t)bz * NN * CC;

    auto load_stage = [&](int ck, int st) {
        const int k0 = ck * 64;
        const uint32_t sb = sbase + st * STG;
        #pragma unroll
        for (int i = 0; i < 8; i++) {
            int c = tid + i * 128;
            int row = c >> 3, cc = c & 7;
            cp_async16(sb + SWZ128((uint32_t)(row * BKB + cc * 16)),
                       A + (size_t)(o0 + row) * CC + k0 + cc * 8);
        }
        #pragma unroll
        for (int i = 0; i < 8; i++) {
            int c = tid + i * 128;
            int row = c >> 3, cc = c & 7;
            cp_async16(sb + B_OFF + SWZ128((uint32_t)(row * BKB + cc * 16)),
                       Bb + (size_t)(n0 + row) * CC + k0 + cc * 8);
        }
        CP_COMMIT();
    };

    float acc[4][8][4];
    #pragma unroll
    for (int mf = 0; mf < 4; mf++)
        #pragma unroll
        for (int nf = 0; nf < 8; nf++)
            #pragma unroll
            for (int e = 0; e < 4; e++) acc[mf][nf][e] = 0.f;

    load_stage(0, 0);
    load_stage(1, 1);
    CP_WAIT(1);
    __syncthreads();

    const int a_row  = wm * 64 + (lane & 15);
    const int a_coff = (lane >> 4) * 16;
    const int b_row  = wn * 64 + ((lane >> 4) << 3) + (lane & 7);
    const int b_coff = ((lane >> 3) & 1) * 16;

    int stc = 0;
    int stp = 2;
    for (int it = 0; it < 8; it++) {
        const uint32_t sb = sbase + stc * STG;
        #pragma unroll
        for (int kk = 0; kk < 4; kk++) {
            uint32_t a[4][4], b[8][2];
            #pragma unroll
            for (int mf = 0; mf < 4; mf++)
                ldmatrix_x4(a[mf], sb +
                            SWZ128((uint32_t)((a_row + mf * 16) * BKB + kk * 32 + a_coff)));
            #pragma unroll
            for (int ng = 0; ng < 4; ng++) {
                uint32_t r[4];
                ldmatrix_x4(r, sb + B_OFF +
                            SWZ128((uint32_t)((b_row + ng * 16) * BKB + kk * 32 + b_coff)));
                b[ng * 2][0] = r[0];  b[ng * 2][1] = r[1];
                b[ng * 2 + 1][0] = r[2];  b[ng * 2 + 1][1] = r[3];
            }
            #pragma unroll
            for (int mf = 0; mf < 4; mf++)
                #pragma unroll
                for (int nf = 0; nf < 8; nf++)
                    mma_f16(acc[mf][nf], a[mf], b[nf]);
        }
        if (it + 2 < 8) {
            load_stage(it + 2, stp);
            CP_WAIT(1);
        } else {
            CP_WAIT(0);
        }
        __syncthreads();
        stc = (stc == 2) ? 0 : stc + 1;
        stp = (stp == 2) ? 0 : stp + 1;
    }

    // ---- epilogue: v tile (fp16) -> smem [128][VP]; k tile -> smem ----
    __half* sv = (__half*)smem;
    const int er = lane >> 2;
    const int ec = (lane & 3) * 2;
    #pragma unroll
    for (int mf = 0; mf < 4; mf++) {
        #pragma unroll
        for (int nf = 0; nf < 8; nf++) {
            const int lr = wm * 64 + mf * 16 + er;
            const int lc = wn * 64 + nf * 8 + ec;
            *(__half2*)&sv[lr * VP + lc] =
                __floats2half2_rn(acc[mf][nf][0], acc[mf][nf][1]);
            *(__half2*)&sv[(lr + 8) * VP + lc] =
                __floats2half2_rn(acc[mf][nf][2], acc[mf][nf][3]);
        }
    }
    const __half* kb = qk + ((size_t)bz * 2 * CC + CC + o0) * NN + n0;
    #pragma unroll
    for (int i = 0; i < 16; i++) {
        int idx = tid + i * 128;
        int r = idx >> 4, c = idx & 15;
        cp_async16(sbase + KV_KOFF + (uint32_t)(r * 272 + c * 16),
                   kb + (size_t)r * NN + c * 8);
    }
    CP_COMMIT();
    CP_WAIT(0);
    __syncthreads();

    const int dgrp = wid;
    const int arow2 = lane & 15;
    const int acoff2 = (lane >> 4) * 16;
    const int bcoff2 = ((lane >> 3) & 1) * 16;
    const uint32_t ones[4] = {ONES2, ONES2, ONES2, ONES2};

    for (int head = 0; head < 2; head++) {
        float kacc[5][2][4];
        #pragma unroll
        for (int m = 0; m < 5; m++)
            #pragma unroll
            for (int nt = 0; nt < 2; nt++)
                #pragma unroll
                for (int e = 0; e < 4; e++) kacc[m][nt][e] = 0.f;

        const int brow2 = head * 64 + dgrp * 16 + ((lane >> 4) << 3) + (lane & 7);
        #pragma unroll
        for (int ks = 0; ks < 8; ks++) {
            uint32_t bf[4];
            ldmatrix_x4(bf, sbase + KV_KOFF + (uint32_t)(brow2 * 272 + ks * 32 + bcoff2));
            uint32_t b0[2] = {bf[0], bf[1]}, b1[2] = {bf[2], bf[3]};
            #pragma unroll
            for (int m = 0; m < 4; m++) {
                uint32_t a[4];
                ldmatrix_x4(a, sbase +
                            (uint32_t)((head * 64 + m * 16 + arow2) * 272 + ks * 32 + acoff2));
                mma_f16(kacc[m][0], a, b0);
                mma_f16(kacc[m][1], a, b1);
            }
            mma_f16(kacc[4][0], ones, b0);
            mma_f16(kacc[4][1], ones, b1);
        }

        const int bh = bz * 8 + blockIdx.y * 2 + head;
        float* outb = kvp + (size_t)blockIdx.x * (128 * 4160) + (size_t)bh * 4160;
        #pragma unroll
        for (int m = 0; m < 4; m++)
            #pragma unroll
            for (int nt = 0; nt < 2; nt++) {
                const int e = m * 16 + (lane >> 2);
                const int d = dgrp * 16 + nt * 8 + 2 * (lane & 3);
                *(float2*)&outb[e * 64 + d]       = make_float2(kacc[m][nt][0], kacc[m][nt][1]);
                *(float2*)&outb[(e + 8) * 64 + d] = make_float2(kacc[m][nt][2], kacc[m][nt][3]);
            }
        if (lane < 4) {
            #pragma unroll
            for (int nt = 0; nt < 2; nt++) {
                const int d = dgrp * 16 + nt * 8 + 2 * lane;
                *(float2*)&outb[4096 + d] = make_float2(kacc[4][nt][0], kacc[4][nt][1]);
            }
        }
    }
}

// ---------------------------------------------------------------------------
// Weight convert (all three in one launch)
// ---------------------------------------------------------------------------
__global__ void conv_w_all(const float* __restrict__ wqk, const float* __restrict__ wv,
                           const float* __restrict__ wo,
                           __half* __restrict__ oq, __half* __restrict__ ov,
                           __half* __restrict__ oo)
{
    int i = blockIdx.x * 256 + threadIdx.x;
    if (i < 524288) {
        oq[i] = __float2half_rn(wqk[i]);
    } else if (i < 786432) {
        int j = i - 524288; ov[j] = __float2half_rn(wv[j]);
    } else if (i < 1048576) {
        int j = i - 786432; oo[j] = __float2half_rn(wo[j]);
    }
}

// ---------------------------------------------------------------------------
// Transpose + fp16 convert (batches bz0 + blockIdx.z)
// ---------------------------------------------------------------------------
__global__ __launch_bounds__(256) void conv_xt_kernel(
    const float* __restrict__ x, const float* __restrict__ pos,
    __half* __restrict__ xq, __half* __restrict__ xv, int bz0)
{
    __shared__ float sA[64][65];
    __shared__ float sB[64][65];

    const int tid = threadIdx.x;
    const int n0 = blockIdx.x * 64;
    const int c0 = blockIdx.y * 64;
    const int bz = bz0 + blockIdx.z;

    const float* i0 = x   + (size_t)bz * CC * NN;
    const float* i1 = pos + (size_t)bz * CC * NN;

    #pragma unroll
    for (int i = 0; i < 4; i++) {
        int idx = i * 256 + tid;
        int rc = idx >> 4, cn = (idx & 15) * 4;
        float4 xv4 = *(const float4*)&i0[(size_t)(c0 + rc) * NN + n0 + cn];
        float4 pv4 = *(const float4*)&i1[(size_t)(c0 + rc) * NN + n0 + cn];
        sA[rc][cn]     = xv4.x + pv4.x;
        sA[rc][cn + 1] = xv4.y + pv4.y;
        sA[rc][cn + 2] = xv4.z + pv4.z;
        sA[rc][cn + 3] = xv4.w + pv4.w;
        sB[rc][cn]     = xv4.x;
        sB[rc][cn + 1] = xv4.y;
        sB[rc][cn + 2] = xv4.z;
        sB[rc][cn + 3] = xv4.w;
    }
    __syncthreads();

    const size_t obase = ((size_t)bz * NN + n0) * CC + c0;
    #pragma unroll
    for (int i = 0; i < 8; i++) {
        int idx = i * 256 + tid;
        int nr = idx >> 5, cp = idx & 31;
        size_t oa = obase + (size_t)nr * CC + cp * 2;
        __half2 hq, hv;
        hq.x = __float2half_rn(sA[cp * 2][nr]);
        hq.y = __float2half_rn(sA[cp * 2 + 1][nr]);
        hv.x = __float2half_rn(sB[cp * 2][nr]);
        hv.y = __float2half_rn(sB[cp * 2 + 1][nr]);
        *(__half2*)(xq + oa) = hq;
        *(__half2*)(xv + oa) = hv;
    }
}

// ---------------------------------------------------------------------------
// kv reduce for one group of bh (GB*8 bh per group)
// ---------------------------------------------------------------------------
__global__ void kv_reduce(const float* __restrict__ kvp, float* __restrict__ kvout,
                          int bh0)
{
    int i = blockIdx.x * 256 + threadIdx.x;
    if (i < GB * 8 * 4160) {
        size_t j = (size_t)bh0 * 4160 + i;
        float s = 0.f;
        #pragma unroll
        for (int c = 0; c < 32; c++) s += kvp[(size_t)c * (128 * 4160) + j];
        kvout[j] = s;
    }
}

// ---------------------------------------------------------------------------
// attn (tensor cores): out[e,n] = (kv @ q)[e,n] / (ksum@q[n] + EPS)
// ---------------------------------------------------------------------------
#define AT_AH 0
#define AT_AL 10240
#define AT_B  20480
#define AT_SCR 36864
#define ATTN_SMEM 55296

__global__ __launch_bounds__(128) void attn_tc_kernel(
    const __half* __restrict__ qk, const float* __restrict__ kv,
    __half* __restrict__ ao, int bh0)
{
    extern __shared__ __align__(1024) char smem[];
    const uint32_t sbase = smem_u32(smem);
    __half* S1   = (__half*)(smem + AT_SCR);
    __half* sOut = (__half*)(smem + AT_SCR);

    const int tid  = threadIdx.x;
    const int wid  = tid >> 5;
    const int lane = tid & 31;
    const int bh   = bh0 + blockIdx.y;
    const int b = bh >> 3, h = bh & 7;
    const int n0 = blockIdx.x * 128;

    const __half* qbase = qk + ((size_t)b * 2 * CC + h * HD) * NN + n0;
    #pragma unroll
    for (int i = 0; i < 8; i++) {
        int idx = tid + i * 128;
        int d = idx >> 4, j = idx & 15;
        cp_async16(sbase + AT_SCR + (uint32_t)(d * 288 + j * 16),
                   qbase + (size_t)d * NN + j * 8);
    }
    CP_COMMIT();

    {
        uint4 z = {0, 0, 0, 0};
        for (int i = tid; i < 1280; i += 128)
            *(uint4*)(smem + AT_AH + i * 16) = z;
    }
    __syncthreads();
    const float* kvb = kv + (size_t)bh * 4160;
    for (int i = tid; i < 4160; i += 128) {
        int e = i >> 6, d = i & 63;
        float f = kvb[i];
        __half hi = __float2half_rn(f);
        __half lo = __float2half_rn(f - __half2float(hi));
        uint32_t off = SWZ128((uint32_t)(e * 128 + d * 2));
        *(__half*)(smem + AT_AH + off) = hi;
        *(__half*)(smem + AT_AL + off) = lo;
    }
    CP_WAIT(0);
    __syncthreads();

    {
        union { __half hh[8]; uint4 u; } pk;
        const int n = tid;
        #pragma unroll
        for (int j = 0; j < 8; j++) {
            #pragma unroll
            for (int d2 = 0; d2 < 8; d2++)
                pk.hh[d2] = S1[(j * 8 + d2) * 144 + n];
            *(uint4*)(smem + AT_B + SWZ128((uint32_t)(n * 128 + j * 16))) = pk.u;
        }
    }
    __syncthreads();

    float acc[5][4][4];
    #pragma unroll
    for (int m = 0; m < 5; m++)
        #pragma unroll
        for (int nt = 0; nt < 4; nt++)
            #pragma unroll
            for (int e = 0; e < 4; e++) acc[m][nt][e] = 0.f;

    const int a_row  = lane & 15;
    const int a_coff = (lane >> 4) * 16;
    const int b_coff = ((lane >> 3) & 1) * 16;

    #pragma unroll
    for (int ks = 0; ks < 4; ks++) {
        uint32_t ah[5][4], al[5][4], bfr[4][2];
        #pragma unroll
        for (int m = 0; m < 5; m++) {
            const uint32_t so = SWZ128((uint32_t)((m * 16 + a_row) * 128 + ks * 32 + a_coff));
            ldmatrix_x4(ah[m], sbase + AT_AH + so);
            ldmatrix_x4(al[m], sbase + AT_AL + so);
        }
        #pragma unroll
        for (int g = 0; g < 2; g++) {
            const int brow = wid * 32 + g * 16 + ((lane >> 4) << 3) + (lane & 7);
            uint32_t r[4];
            ldmatrix_x4(r, sbase + AT_B + SWZ128((uint32_t)(brow * 128 + ks * 32 + b_coff)));
            bfr[g * 2][0] = r[0];  bfr[g * 2][1] = r[1];
            bfr[g * 2 + 1][0] = r[2];  bfr[g * 2 + 1][1] = r[3];
        }
        #pragma unroll
        for (int m = 0; m < 5; m++)
            #pragma unroll
            for (int nt = 0; nt < 4; nt++) {
                mma_f16(acc[m][nt], ah[m], bfr[nt]);
                mma_f16(acc[m][nt], al[m], bfr[nt]);
            }
    }

    #pragma unroll
    for (int nt = 0; nt < 4; nt++) {
        float den0 = __shfl_sync(0xffffffffu, acc[4][nt][0], lane & 3);
        float den1 = __shfl_sync(0xffffffffu, acc[4][nt][1], lane & 3);
        float inv0 = 1.f / (den0 + EPS);
        float inv1 = 1.f / (den1 + EPS);
        const int n = wid * 32 + nt * 8 + 2 * (lane & 3);
        #pragma unroll
        for (int m = 0; m < 4; m++) {
            const int e = m * 16 + (lane >> 2);
            sOut[n * 72 + e]           = __float2half_rn(acc[m][nt][0] * inv0);
            sOut[(n + 1) * 72 + e]     = __float2half_rn(acc[m][nt][1] * inv1);
            sOut[n * 72 + e + 8]       = __float2half_rn(acc[m][nt][2] * inv0);
            sOut[(n + 1) * 72 + e + 8] = __float2half_rn(acc[m][nt][3] * inv1);
        }
    }
    __syncthreads();

    {
        const int n = tid;
        __half* dst = ao + ((size_t)b * NN + n0 + n) * CC + h * HD;
        #pragma unroll
        for (int j = 0; j < 8; j++)
            *(uint4*)(dst + j * 8) = *(uint4*)(sOut + n * 72 + j * 8);
    }
}

// ---------------------------------------------------------------------------
extern "C" void kernel_launch(void* const* d_in, const int* in_sizes, int n_in,
                              void* d_out, int out_size)
{
    const float* x    = (const float*)d_in[0];
    const float* pos  = (const float*)d_in[1];
    const float* w_qk = (const float*)d_in[2];
    const float* w_v  = (const float*)d_in[3];
    const float* w_o  = (const float*)d_in[4];
    float* out = (float*)d_out;

    __half *qk;
    float *kvp, *kvr;
    cudaGetSymbolAddress((void**)&qk,  g_qkh);
    cudaGetSymbolAddress((void**)&kvp, g_kvp);
    cudaGetSymbolAddress((void**)&kvr, g_kv);
    __half *xq, *xv, *ao, *wq, *wv, *wo;
    cudaGetSymbolAddress((void**)&xq, g_xq);
    cudaGetSymbolAddress((void**)&xv, g_xv);
    cudaGetSymbolAddress((void**)&ao, g_ao);
    cudaGetSymbolAddress((void**)&wq, g_wqk);
    cudaGetSymbolAddress((void**)&wv, g_wv);
    cudaGetSymbolAddress((void**)&wo, g_wo);

    cudaFuncSetAttribute(gemm_tc<true, true>,
                         cudaFuncAttributeMaxDynamicSharedMemorySize, GEMM_SMEM);
    cudaFuncSetAttribute(gemm_tc<false, false>,
                         cudaFuncAttributeMaxDynamicSharedMemorySize, GEMM_SMEM);
    cudaFuncSetAttribute(gemm_v_kv,
                         cudaFuncAttributeMaxDynamicSharedMemorySize, GEMM_SMEM);
    cudaFuncSetAttribute(attn_tc_kernel,
                         cudaFuncAttributeMaxDynamicSharedMemorySize, ATTN_SMEM);

    // 8 groups of 2 batches on the proven 4-lane stream layout: stream lane s
    // runs groups s and s+4 back-to-back. Finer launch granularity = shorter
    // tail waves + natural interleave of memory phases under GEMM phases.
    // Handles created once per process (same envelope as R11/R16 champions).
    static cudaStream_t s_st[NSTR - 1];
    static cudaEvent_t  s_evRoot;
    static cudaEvent_t  s_evDone[NSTR - 1];
    static bool s_init = false;
    if (!s_init) {
        for (int g = 0; g < NSTR - 1; g++)
            cudaStreamCreateWithFlags(&s_st[g], cudaStreamNonBlocking);
        cudaEventCreateWithFlags(&s_evRoot, cudaEventDisableTiming);
        for (int g = 0; g < NSTR - 1; g++)
            cudaEventCreateWithFlags(&s_evDone[g], cudaEventDisableTiming);
        s_init = true;
    }

    // 0) weight converts on origin stream
    conv_w_all<<<4096, 256>>>(w_qk, w_v, w_o, wq, wv, wo);
    cudaEventRecord(s_evRoot, 0);

    auto chain = [&](int g, cudaStream_t stm) {
        const int bz0 = g * GB;
        const int bh0 = bz0 * NH;

        conv_xt_kernel<<<dim3(NN / 64, CC / 64, GB), 256, 0, stm>>>(
            x, pos, xq, xv, bz0);
        gemm_tc<true, true><<<dim3(NN / 128, 1024 / 128, GB), 128, GEMM_SMEM, stm>>>(
            wq, xq, qk, 1024, bz0);
        gemm_v_kv<<<dim3(NN / 128, 512 / 128, GB), 128, GEMM_SMEM, stm>>>(
            wv, xv, qk, kvp, bz0);
        kv_reduce<<<(GB * 8 * 4160 + 255) / 256, 256, 0, stm>>>(kvp, kvr, bh0);
        attn_tc_kernel<<<dim3(NN / 128, GB * 8), 128, ATTN_SMEM, stm>>>(
            qk, kvr, ao, bh0);
        gemm_tc<false, false><<<dim3(NN / 128, 512 / 128, GB), 128, GEMM_SMEM, stm>>>(
            wo, ao, out, 512, bz0);
    };

    // stream lane 0 = origin: groups 0 and 4 (ordered after conv_w_all implicitly)
    chain(0, (cudaStream_t)0);
    chain(4, (cudaStream_t)0);

    // lanes 1..3 on forked streams: groups s and s+4
    for (int s = 1; s < NSTR; s++) {
        cudaStreamWaitEvent(s_st[s - 1], s_evRoot, 0);
        chain(s, s_st[s - 1]);
        chain(s + 4, s_st[s - 1]);
        cudaEventRecord(s_evDone[s - 1], s_st[s - 1]);
    }

    // join all branches back to the origin stream
    for (int g = 0; g < NSTR - 1; g++)
        cudaStreamWaitEvent(0, s_evDone[g], 0);
}